// round 14
// baseline (speedup 1.0000x reference)
#include <cuda_runtime.h>
#include <cuda_fp16.h>
#include <math.h>
#include <stdint.h>

#define BATCH  2
#define SEQ    2048
#define DIM    1024
#define NH     16
#define NG     4
#define GRP    4
#define HDIM   64
#define FF     4096
#define NL     8
#define VOCAB  32000
#define WIN    1024
#define EPS    1e-6f
#define NTOK   (BATCH*SEQ)   // 4096
#define QKVW   1536
#define F2W    8192
#define INV2048 (1.0f/2048.0f)

// ======================= scratch =======================
__device__ float g_x   [NTOK*DIM];
__device__ float g_qkv [NTOK*QKVW];
__device__ float g_t   [NTOK*DIM];

__device__ __align__(128) __half g_a_h[NTOK*DIM];
__device__ __align__(128) __half g_a_l[NTOK*DIM];
__device__ __align__(128) __half g_b_h[NTOK*FF];
__device__ __align__(128) __half g_b_l[NTOK*FF];
__device__ __align__(128) __half g_wqkv[NL*QKVW*1024];
__device__ __align__(128) __half g_wot [NL*1024*1024];
__device__ __align__(128) __half g_w12 [NL*F2W*1024];
__device__ __align__(128) __half g_w3t [NL*1024*4096];
__device__ __align__(128) __half g_emb [VOCAB*DIM];

// ======================= small kernels =======================
__global__ void embed_kernel(const int* __restrict__ ids,
                             const float* __restrict__ emb,
                             float* __restrict__ x) {
    int t = blockIdx.x;
    int id = ids[t];
    const float* e = emb + (size_t)id * DIM;
    float* xp = x + (size_t)t * DIM;
    for (int d = threadIdx.x; d < DIM; d += blockDim.x)
        xp[d] = e[d] * 32.0f;
}

__global__ void half_kernel(const float* __restrict__ in,
                            __half* __restrict__ o, int n) {
    int i = blockIdx.x * 256 + threadIdx.x;
    if (i < n) o[i] = __float2half(in[i]);
}

// transpose to fp16 packed: W [L,K,N] fp32 -> out [L, prow(n), K]
__global__ void wconv_kernel(const float* __restrict__ W,
                             __half* __restrict__ o,
                             int K, int N, size_t lstride, int rowoff, int mode) {
    __shared__ float t[32][33];
    int l = blockIdx.z;
    const float* Wl = W + (size_t)l * K * N;
    size_t ob = (size_t)l * lstride;
    int n0 = blockIdx.x * 32, k0 = blockIdx.y * 32;
    int tx = threadIdx.x, ty = threadIdx.y;
#pragma unroll
    for (int r = 0; r < 32; r += 8)
        t[ty + r][tx] = Wl[(size_t)(k0 + ty + r) * N + n0 + tx];
    __syncthreads();
#pragma unroll
    for (int r = 0; r < 32; r += 8) {
        int n = n0 + ty + r;
        int prow;
        if (mode == 0)      prow = rowoff + n;
        else if (mode == 1) prow = ((n >> 6) << 7) + (n & 63);
        else                prow = ((n >> 6) << 7) + 64 + (n & 63);
        o[ob + (size_t)prow * K + k0 + tx] = __float2half(t[tx][ty + r]);
    }
}

// merged QKV weight conversion
__global__ void wconv_qkv_kernel(const float* __restrict__ Wq,
                                 const float* __restrict__ Wk,
                                 const float* __restrict__ Wv,
                                 __half* __restrict__ o) {
    __shared__ float t[32][33];
    int l = blockIdx.z;
    int n0 = blockIdx.x * 32, k0 = blockIdx.y * 32;
    int tx = threadIdx.x, ty = threadIdx.y;
    const float* W; int srcN, coff;
    if (n0 < 1024)      { W = Wq; srcN = 1024; coff = 0; }
    else if (n0 < 1280) { W = Wk; srcN = 256;  coff = 1024; }
    else                { W = Wv; srcN = 256;  coff = 1280; }
    const float* Wl = W + (size_t)l * 1024 * srcN;
    size_t ob = (size_t)l * QKVW * 1024;
#pragma unroll
    for (int r = 0; r < 32; r += 8)
        t[ty + r][tx] = Wl[(size_t)(k0 + ty + r) * srcN + (n0 - coff) + tx];
    __syncthreads();
#pragma unroll
    for (int r = 0; r < 32; r += 8)
        o[ob + (size_t)(n0 + ty + r) * 1024 + k0 + tx] = __float2half(t[tx][ty + r]);
}

__device__ __forceinline__ uint2 pack4h(float v0, float v1, float v2, float v3) {
    __half2 a = __halves2half2(__float2half(v0), __float2half(v1));
    __half2 b = __halves2half2(__float2half(v2), __float2half(v3));
    uint2 r;
    r.x = *(uint32_t*)&a;
    r.y = *(uint32_t*)&b;
    return r;
}

__global__ __launch_bounds__(256) void rmsnorm_split_kernel(const float* __restrict__ in,
                                                            const float* __restrict__ scale,
                                                            __half* __restrict__ oh,
                                                            __half* __restrict__ ol) {
    const int t = blockIdx.x;
    const int tid = threadIdx.x;
    float4 xv = ((const float4*)(in + (size_t)t * DIM))[tid];
    float ss = xv.x * xv.x + xv.y * xv.y + xv.z * xv.z + xv.w * xv.w;
    __shared__ float red[256];
    red[tid] = ss; __syncthreads();
    for (int o = 128; o > 0; o >>= 1) {
        if (tid < o) red[tid] += red[tid + o];
        __syncthreads();
    }
    const float r = rsqrtf(red[0] * (1.0f / DIM) + EPS);
    float4 sc = ((const float4*)scale)[tid];
    float v0 = xv.x * r * (1.0f + sc.x);
    float v1 = xv.y * r * (1.0f + sc.y);
    float v2 = xv.z * r * (1.0f + sc.z);
    float v3 = xv.w * r * (1.0f + sc.w);
    uint2 hh = pack4h(v0, v1, v2, v3);
    __half2* hp = (__half2*)&hh;
    float l0 = v0 - __low2float(hp[0]),  l1 = v1 - __high2float(hp[0]);
    float l2 = v2 - __low2float(hp[1]),  l3 = v3 - __high2float(hp[1]);
    ((uint2*)(oh + (size_t)t * DIM))[tid] = hh;
    ((uint2*)(ol + (size_t)t * DIM))[tid] = pack4h(l0, l1, l2, l3);
}

// x += rmsnorm(t, sa); then out = rmsnorm(x, so) -> split fp16 (vectorized)
__global__ __launch_bounds__(256) void fuse_norm_kernel(float* __restrict__ x,
                                                        const float* __restrict__ t,
                                                        const float* __restrict__ sa,
                                                        const float* __restrict__ so,
                                                        __half* __restrict__ oh,
                                                        __half* __restrict__ ol) {
    const int tk = blockIdx.x;
    const int tid = threadIdx.x;
    float4 tv = ((const float4*)(t + (size_t)tk * DIM))[tid];
    float ss = tv.x * tv.x + tv.y * tv.y + tv.z * tv.z + tv.w * tv.w;
    __shared__ float red[256];
    red[tid] = ss; __syncthreads();
    for (int o = 128; o > 0; o >>= 1) {
        if (tid < o) red[tid] += red[tid + o];
        __syncthreads();
    }
    const float r1 = rsqrtf(red[0] * (1.0f / DIM) + EPS);
    __syncthreads();
    float4 sa4 = ((const float4*)sa)[tid];
    float4* xp4 = (float4*)(x + (size_t)tk * DIM);
    float4 xv = xp4[tid];
    xv.x += tv.x * r1 * (1.0f + sa4.x);
    xv.y += tv.y * r1 * (1.0f + sa4.y);
    xv.z += tv.z * r1 * (1.0f + sa4.z);
    xv.w += tv.w * r1 * (1.0f + sa4.w);
    float ss2 = xv.x * xv.x + xv.y * xv.y + xv.z * xv.z + xv.w * xv.w;
    xp4[tid] = xv;
    red[tid] = ss2; __syncthreads();
    for (int o = 128; o > 0; o >>= 1) {
        if (tid < o) red[tid] += red[tid + o];
        __syncthreads();
    }
    const float r2 = rsqrtf(red[0] * (1.0f / DIM) + EPS);
    float4 so4 = ((const float4*)so)[tid];
    float v0 = xv.x * r2 * (1.0f + so4.x);
    float v1 = xv.y * r2 * (1.0f + so4.y);
    float v2 = xv.z * r2 * (1.0f + so4.z);
    float v3 = xv.w * r2 * (1.0f + so4.w);
    uint2 hh = pack4h(v0, v1, v2, v3);
    __half2* hp = (__half2*)&hh;
    float l0 = v0 - __low2float(hp[0]),  l1 = v1 - __high2float(hp[0]);
    float l2 = v2 - __low2float(hp[1]),  l3 = v3 - __high2float(hp[1]);
    ((uint2*)(oh + (size_t)tk * DIM))[tid] = hh;
    ((uint2*)(ol + (size_t)tk * DIM))[tid] = pack4h(l0, l1, l2, l3);
}

// merged q+k rmsnorm+rope
__global__ __launch_bounds__(64) void qkrope_kernel(float* __restrict__ x,
                                                    const float* __restrict__ qsc,
                                                    const float* __restrict__ ksc,
                                                    const float* __restrict__ cosb,
                                                    const float* __restrict__ sinb) {
    const int token = blockIdx.x;
    const int hh = blockIdx.y;
    const int pos = token % SEQ;
    const int d = threadIdx.x;
    const float* scale = (hh < NH) ? qsc : ksc;
    const int off = (hh < NH) ? hh * HDIM : 1024 + (hh - NH) * HDIM;
    float* xp = x + (size_t)token * QKVW + off;
    const float val = xp[d];
    __shared__ float sh[HDIM];
    sh[d] = val * val;
    __syncthreads();
    for (int o = 32; o > 0; o >>= 1) {
        if (d < o) sh[d] += sh[d + o];
        __syncthreads();
    }
    const float r = rsqrtf(sh[0] * (1.0f / HDIM) + EPS);
    __syncthreads();
    const float nv = val * r * (1.0f + scale[d]);
    sh[d] = nv;
    __syncthreads();
    const float rot = (d < 32) ? -sh[d + 32] : sh[d - 32];
    xp[d] = nv * cosb[pos * HDIM + d] + rot * sinb[pos * HDIM + d];
}

// ======================= mma helpers =======================
__device__ __forceinline__ uint32_t smem_u32(const void* p) {
    uint32_t a;
    asm("{ .reg .u64 t; cvta.to.shared.u64 t, %1; cvt.u32.u64 %0, t; }" : "=r"(a) : "l"(p));
    return a;
}
__device__ __forceinline__ void cp16(uint32_t s, const void* g) {
    asm volatile("cp.async.cg.shared.global [%0], [%1], 16;" :: "r"(s), "l"(g));
}
#define LDMX4(r0, r1, r2, r3, addr) \
    asm volatile("ldmatrix.sync.aligned.m8n8.x4.shared.b16 {%0,%1,%2,%3}, [%4];" \
        : "=r"(r0), "=r"(r1), "=r"(r2), "=r"(r3) : "r"(addr))
#define LDMX4T(r0, r1, r2, r3, addr) \
    asm volatile("ldmatrix.sync.aligned.m8n8.x4.trans.shared.b16 {%0,%1,%2,%3}, [%4];" \
        : "=r"(r0), "=r"(r1), "=r"(r2), "=r"(r3) : "r"(addr))
#define MMA16816(d, a, b) \
    asm volatile("mma.sync.aligned.m16n8k16.row.col.f32.f16.f16.f32 " \
        "{%0,%1,%2,%3}, {%4,%5,%6,%7}, {%8,%9}, {%0,%1,%2,%3};" \
        : "+f"((d)[0]), "+f"((d)[1]), "+f"((d)[2]), "+f"((d)[3]) \
        : "r"((a)[0]), "r"((a)[1]), "r"((a)[2]), "r"((a)[3]), "r"((b)[0]), "r"((b)[1]))
#define MMA16816H(d, a, b) \
    asm volatile("mma.sync.aligned.m16n8k16.row.col.f16.f16.f16.f16 " \
        "{%0,%1}, {%2,%3,%4,%5}, {%6,%7}, {%0,%1};" \
        : "+r"((d)[0]), "+r"((d)[1]) \
        : "r"((a)[0]), "r"((a)[1]), "r"((a)[2]), "r"((a)[3]), "r"((b)[0]), "r"((b)[1]))

// ======================= flash attention (tensor core, 2-limb fp16) =======================
#define FSW(r, u) ((r)*128 + (((u) ^ ((r)&7)) << 4))

__device__ __forceinline__ void fa_cvt_store(char* hbuf, char* lbuf, int r, int u,
                                             const float* src, float scale) {
    float4 f0 = *(const float4*)src;
    float4 f1 = *(const float4*)(src + 4);
    float v[8] = {f0.x, f0.y, f0.z, f0.w, f1.x, f1.y, f1.z, f1.w};
    __half hv[8], lv[8];
#pragma unroll
    for (int i = 0; i < 8; i++) {
        float x = v[i] * scale;
        __half hh = __float2half(x);
        hv[i] = hh;
        lv[i] = __float2half((x - __half2float(hh)) * 2048.0f);
    }
    uint32_t off = FSW(r, u);
    *(uint4*)(hbuf + off) = *(uint4*)hv;
    *(uint4*)(lbuf + off) = *(uint4*)lv;
}

__global__ __launch_bounds__(128) void flash_mma(const float* __restrict__ qkv,
                                                 __half* __restrict__ oh,
                                                 __half* __restrict__ ol,
                                                 int window) {
    __shared__ __align__(128) char sm[32768];
    char* khb = sm;
    char* klb = sm + 8192;
    char* vhb = sm + 16384;
    char* vlb = sm + 24576;
    const uint32_t khs = smem_u32(khb);
    const uint32_t kls = khs + 8192;
    const uint32_t vhs = khs + 16384;
    const uint32_t vls = khs + 24576;

    const int qt = blockIdx.x, b = blockIdx.y, h = blockIdx.z;
    const int g = h / GRP;
    const int tid = threadIdx.x;
    const int w = tid >> 5, lane = tid & 31;
    const int q0 = qt * 64;

    for (int task = tid; task < 512; task += 128) {
        int r = task >> 3, u = task & 7;
        fa_cvt_store(khb, klb, r, u,
                     qkv + (size_t)(b * SEQ + q0 + r) * QKVW + h * HDIM + u * 8, 0.125f);
    }
    __syncthreads();
    uint32_t qfh[4][4], qfl[4][4];
    {
        int row = w * 16 + (lane & 15);
#pragma unroll
        for (int ks = 0; ks < 4; ks++) {
            int u = ks * 2 + (lane >> 4);
            LDMX4(qfh[ks][0], qfh[ks][1], qfh[ks][2], qfh[ks][3], khs + FSW(row, u));
            LDMX4(qfl[ks][0], qfl[ks][1], qfl[ks][2], qfl[ks][3], kls + FSW(row, u));
        }
    }

    float accH[8][4] = {}, accL[8][4] = {};
    float mrun0 = -1e30f, mrun1 = -1e30f, srun0 = 0.f, srun1 = 0.f;

    const int i0 = q0 + w * 16 + (lane >> 2);
    const int i1 = i0 + 8;

    int t0 = 0;
    if (window > 0) { int lo = q0 - window; if (lo > 0) t0 = lo >> 6; }

    for (int kt = t0; kt <= qt; kt++) {
        const int k0 = kt * 64;
        __syncthreads();
        for (int task = tid; task < 512; task += 128) {
            int r = task >> 3, u = task & 7;
            size_t base = (size_t)(b * SEQ + k0 + r) * QKVW + g * HDIM + u * 8;
            fa_cvt_store(khb, klb, r, u, qkv + base + 1024, 1.0f);
            fa_cvt_store(vhb, vlb, r, u, qkv + base + 1280, 1.0f);
        }
        __syncthreads();

        float sH[8][4] = {}, sL[8][4] = {};
#pragma unroll
        for (int ks = 0; ks < 4; ks++) {
            const int bm = lane >> 3;
            const int brow = ((bm >> 1) << 3) + (lane & 7);
            const int bu = ks * 2 + (bm & 1);
#pragma unroll
            for (int p2 = 0; p2 < 4; p2++) {
                uint32_t bh[2][2], bl[2][2];
                uint32_t t0r, t1r, t2r, t3r;
                LDMX4(t0r, t1r, t2r, t3r, khs + FSW(p2 * 16 + brow, bu));
                bh[0][0] = t0r; bh[0][1] = t1r; bh[1][0] = t2r; bh[1][1] = t3r;
                LDMX4(t0r, t1r, t2r, t3r, kls + FSW(p2 * 16 + brow, bu));
                bl[0][0] = t0r; bl[0][1] = t1r; bl[1][0] = t2r; bl[1][1] = t3r;
#pragma unroll
                for (int q2 = 0; q2 < 2; q2++) {
                    int nt = p2 * 2 + q2;
                    MMA16816(sH[nt], qfh[ks], bh[q2]);
                    MMA16816(sL[nt], qfl[ks], bh[q2]);
                    MMA16816(sL[nt], qfh[ks], bl[q2]);
                }
            }
        }

        float mt0 = -1e30f, mt1 = -1e30f;
#pragma unroll
        for (int nt = 0; nt < 8; nt++) {
            int j0 = k0 + nt * 8 + 2 * (lane & 3);
            int j1 = j0 + 1;
            bool v00 = (j0 <= i0) && (window == 0 || i0 - j0 <= window);
            bool v01 = (j1 <= i0) && (window == 0 || i0 - j1 <= window);
            bool v10 = (j0 <= i1) && (window == 0 || i1 - j0 <= window);
            bool v11 = (j1 <= i1) && (window == 0 || i1 - j1 <= window);
            sH[nt][0] = v00 ? sH[nt][0] + sL[nt][0] * INV2048 : -1e30f;
            sH[nt][1] = v01 ? sH[nt][1] + sL[nt][1] * INV2048 : -1e30f;
            sH[nt][2] = v10 ? sH[nt][2] + sL[nt][2] * INV2048 : -1e30f;
            sH[nt][3] = v11 ? sH[nt][3] + sL[nt][3] * INV2048 : -1e30f;
            mt0 = fmaxf(mt0, fmaxf(sH[nt][0], sH[nt][1]));
            mt1 = fmaxf(mt1, fmaxf(sH[nt][2], sH[nt][3]));
        }
        mt0 = fmaxf(mt0, __shfl_xor_sync(0xffffffffu, mt0, 1));
        mt0 = fmaxf(mt0, __shfl_xor_sync(0xffffffffu, mt0, 2));
        mt1 = fmaxf(mt1, __shfl_xor_sync(0xffffffffu, mt1, 1));
        mt1 = fmaxf(mt1, __shfl_xor_sync(0xffffffffu, mt1, 2));

        const float mn0 = fmaxf(mrun0, mt0);
        const float mn1 = fmaxf(mrun1, mt1);
        const float al0 = __expf(mrun0 - mn0);
        const float al1 = __expf(mrun1 - mn1);
        mrun0 = mn0; mrun1 = mn1;

        float rs0 = 0.f, rs1 = 0.f;
#pragma unroll
        for (int nt = 0; nt < 8; nt++) {
            sH[nt][0] = __expf(sH[nt][0] - mn0);
            sH[nt][1] = __expf(sH[nt][1] - mn0);
            sH[nt][2] = __expf(sH[nt][2] - mn1);
            sH[nt][3] = __expf(sH[nt][3] - mn1);
            rs0 += sH[nt][0] + sH[nt][1];
            rs1 += sH[nt][2] + sH[nt][3];
        }
        rs0 += __shfl_xor_sync(0xffffffffu, rs0, 1);
        rs0 += __shfl_xor_sync(0xffffffffu, rs0, 2);
        rs1 += __shfl_xor_sync(0xffffffffu, rs1, 1);
        rs1 += __shfl_xor_sync(0xffffffffu, rs1, 2);
        srun0 = srun0 * al0 + rs0;
        srun1 = srun1 * al1 + rs1;

#pragma unroll
        for (int nt = 0; nt < 8; nt++) {
            accH[nt][0] *= al0; accH[nt][1] *= al0; accH[nt][2] *= al1; accH[nt][3] *= al1;
            accL[nt][0] *= al0; accL[nt][1] *= al0; accL[nt][2] *= al1; accL[nt][3] *= al1;
        }

        uint32_t pah[4][4], pal[4][4];
#pragma unroll
        for (int j = 0; j < 4; j++) {
#pragma unroll
            for (int q2 = 0; q2 < 2; q2++) {
                int nt = 2 * j + q2;
#pragma unroll
                for (int half_ = 0; half_ < 2; half_++) {
                    float p0 = sH[nt][half_ * 2 + 0];
                    float p1 = sH[nt][half_ * 2 + 1];
                    __half h0 = __float2half(p0), h1 = __float2half(p1);
                    __half l0 = __float2half((p0 - __half2float(h0)) * 2048.0f);
                    __half l1 = __float2half((p1 - __half2float(h1)) * 2048.0f);
                    __half2 hp = __halves2half2(h0, h1);
                    __half2 lp = __halves2half2(l0, l1);
                    pah[j][q2 * 2 + half_] = *(uint32_t*)&hp;
                    pal[j][q2 * 2 + half_] = *(uint32_t*)&lp;
                }
            }
        }

        {
            const int vrow_base = ((lane >> 3) & 1) * 8 + (lane & 7);
            const int vu_add = lane >> 4;
#pragma unroll
            for (int ks = 0; ks < 4; ks++) {
#pragma unroll
                for (int d2 = 0; d2 < 4; d2++) {
                    int row = ks * 16 + vrow_base;
                    int u = 2 * d2 + vu_add;
                    uint32_t t0r, t1r, t2r, t3r;
                    uint32_t vbh[2][2], vbl[2][2];
                    LDMX4T(t0r, t1r, t2r, t3r, vhs + FSW(row, u));
                    vbh[0][0] = t0r; vbh[0][1] = t1r; vbh[1][0] = t2r; vbh[1][1] = t3r;
                    LDMX4T(t0r, t1r, t2r, t3r, vls + FSW(row, u));
                    vbl[0][0] = t0r; vbl[0][1] = t1r; vbl[1][0] = t2r; vbl[1][1] = t3r;
#pragma unroll
                    for (int dd = 0; dd < 2; dd++) {
                        int nt = 2 * d2 + dd;
                        MMA16816(accH[nt], pah[ks], vbh[dd]);
                        MMA16816(accL[nt], pal[ks], vbh[dd]);
                        MMA16816(accL[nt], pah[ks], vbl[dd]);
                    }
                }
            }
        }
    }

    const float inv0 = 1.0f / srun0;
    const float inv1 = 1.0f / srun1;
    const size_t tok0 = (size_t)(b * SEQ) + q0 + w * 16 + (lane >> 2);
    const size_t tok1 = tok0 + 8;
#pragma unroll
    for (int nt = 0; nt < 8; nt++) {
        int col = h * HDIM + nt * 8 + 2 * (lane & 3);
        float o00 = (accH[nt][0] + accL[nt][0] * INV2048) * inv0;
        float o01 = (accH[nt][1] + accL[nt][1] * INV2048) * inv0;
        float o10 = (accH[nt][2] + accL[nt][2] * INV2048) * inv1;
        float o11 = (accH[nt][3] + accL[nt][3] * INV2048) * inv1;
        __half h00 = __float2half(o00), h01 = __float2half(o01);
        __half h10 = __float2half(o10), h11 = __float2half(o11);
        __half2 hi0 = __halves2half2(h00, h01);
        __half2 hi1 = __halves2half2(h10, h11);
        __half2 lo0 = __halves2half2(__float2half(o00 - __half2float(h00)),
                                     __float2half(o01 - __half2float(h01)));
        __half2 lo1 = __halves2half2(__float2half(o10 - __half2float(h10)),
                                     __float2half(o11 - __half2float(h11)));
        *(__half2*)(oh + tok0 * DIM + col) = hi0;
        *(__half2*)(ol + tok0 * DIM + col) = lo0;
        *(__half2*)(oh + tok1 * DIM + col) = hi1;
        *(__half2*)(ol + tok1 * DIM + col) = lo1;
    }
}

// ======================= fp16 GEMM: 8 warps, single frag, 3-stage, 2 CTAs/SM =======================
#define SSTG      24576
#define NSTAGE    3
#define GSMEM     (NSTAGE*SSTG)   // 72 KB -> 2 CTAs/SM (144KB of 228KB)

struct Frag {
    uint32_t a[2][2][4];
    uint32_t b[8][2];
};

template<int TP>
__device__ __forceinline__ void load_frags(Frag& f, uint32_t st, int ks,
                                           int a_r, int a_uadd, int b_r0, int b_uadd) {
#pragma unroll
    for (int mb = 0; mb < 2; mb++) {
        int r = a_r + mb * 16;
        int u = ks * 2 + a_uadd;
        uint32_t off = r * 64 + ((u ^ ((r >> 1) & 3)) << 4);
        LDMX4(f.a[0][mb][0], f.a[0][mb][1], f.a[0][mb][2], f.a[0][mb][3], st + off);
        if (TP)
            LDMX4(f.a[1][mb][0], f.a[1][mb][1], f.a[1][mb][2], f.a[1][mb][3], st + 8192 + off);
    }
#pragma unroll
    for (int qd = 0; qd < 4; qd++) {
        int r = b_r0 + qd * 16;
        int u = ks * 2 + b_uadd;
        uint32_t off = r * 64 + ((u ^ ((r >> 1) & 3)) << 4);
        uint32_t t0, t1, t2, t3;
        LDMX4(t0, t1, t2, t3, st + 16384 + off);
        f.b[2*qd][0] = t0; f.b[2*qd][1] = t1;
        f.b[2*qd+1][0] = t2; f.b[2*qd+1][1] = t3;
    }
}

template<int TP>
__device__ __forceinline__ void do_mma(float accH[2][8][4], uint32_t accL[2][8][2],
                                       const Frag& f) {
#pragma unroll
    for (int mb = 0; mb < 2; mb++)
#pragma unroll
        for (int nb = 0; nb < 8; nb++) {
            MMA16816(accH[mb][nb], f.a[0][mb], f.b[nb]);
            if (TP)
                MMA16816H(accL[mb][nb], f.a[1][mb], f.b[nb]);
        }
}

template<int TP>
__device__ __forceinline__ void stage_load(uint32_t st,
                                           const __half* Ah, const __half* Al,
                                           const __half* Bh,
                                           int m0, int n0, int k0, int K, int tid) {
#pragma unroll
    for (int c = tid; c < 512; c += 256) {
        int r = c >> 2, u = c & 3;
        uint32_t off = r * 64 + ((u ^ ((r >> 1) & 3)) << 4);
        size_t ga = (size_t)(m0 + r) * K + k0 + u * 8;
        size_t gb = (size_t)(n0 + r) * K + k0 + u * 8;
        cp16(st + off,          Ah + ga);
        if (TP)
            cp16(st + 8192 + off, Al + ga);
        cp16(st + 16384 + off,  Bh + gb);
    }
    asm volatile("cp.async.commit_group;" ::: "memory");
}

template<int TP>
__global__ __launch_bounds__(256, 2) void gemm_fp16(
    const __half* __restrict__ Ah, const __half* __restrict__ Al,
    const __half* __restrict__ Bh,
    float* __restrict__ C, __half* __restrict__ oh, __half* __restrict__ ol,
    int N, int K, int silu)
{
    extern __shared__ __align__(128) char smem[];
    const uint32_t sb = smem_u32(smem);
    const int tid = threadIdx.x;
    const int lane = tid & 31;
    const int w = tid >> 5;
    const int wm = w & 3;
    const int wn = w >> 2;
    const int m0 = blockIdx.x * 128;
    const int n0 = blockIdx.y * 128;
    const int niter = K >> 5;

    float accH[2][8][4] = {};
    uint32_t accL[2][8][2] = {};
    Frag f;

    stage_load<TP>(sb + 0*SSTG, Ah, Al, Bh, m0, n0, 0,  K, tid);
    stage_load<TP>(sb + 1*SSTG, Ah, Al, Bh, m0, n0, 32, K, tid);

    const int a_r = wm * 32 + (lane & 15);
    const int a_uadd = lane >> 4;
    const int b_mat = lane >> 3;
    const int b_r0 = wn * 64 + ((b_mat >> 1) << 3) + (lane & 7);
    const int b_uadd = b_mat & 1;

    for (int it = 0; it < niter; it++) {
        if (it + 2 < niter) { asm volatile("cp.async.wait_group 1;" ::: "memory"); }
        else                { asm volatile("cp.async.wait_group 0;" ::: "memory"); }
        __syncthreads();
        if (it + 2 < niter)
            stage_load<TP>(sb + ((it + 2) % 3) * SSTG, Ah, Al, Bh, m0, n0, (it + 2) * 32, K, tid);

        const uint32_t st = sb + (it % 3) * SSTG;
#pragma unroll
        for (int ks = 0; ks < 2; ks++) {
            load_frags<TP>(f, st, ks, a_r, a_uadd, b_r0, b_uadd);
            do_mma<TP>(accH, accL, f);
        }
        __syncthreads();
    }

    if (!silu) {
#pragma unroll
        for (int mb = 0; mb < 2; mb++) {
            int row = m0 + wm * 32 + mb * 16 + (lane >> 2);
#pragma unroll
            for (int nb = 0; nb < 8; nb++) {
                int col = n0 + wn * 64 + nb * 8 + 2 * (lane & 3);
                float c0 = accH[mb][nb][0];
                float c1 = accH[mb][nb][1];
                float c2 = accH[mb][nb][2];
                float c3 = accH[mb][nb][3];
                if (TP) {
                    __half2 l01 = *(__half2*)&accL[mb][nb][0];
                    __half2 l23 = *(__half2*)&accL[mb][nb][1];
                    c0 += __low2float(l01);  c1 += __high2float(l01);
                    c2 += __low2float(l23);  c3 += __high2float(l23);
                }
                *(float2*)(C + (size_t)row * N + col)       = make_float2(c0, c1);
                *(float2*)(C + (size_t)(row + 8) * N + col) = make_float2(c2, c3);
            }
        }
    } else {
        float* smf = (float*)smem;   // 128 x 132 fp32 = 67.6KB <= 72KB
#pragma unroll
        for (int mb = 0; mb < 2; mb++) {
            int rl = wm * 32 + mb * 16 + (lane >> 2);
#pragma unroll
            for (int nb = 0; nb < 8; nb++) {
                int cl = wn * 64 + nb * 8 + 2 * (lane & 3);
                __half2 l01 = *(__half2*)&accL[mb][nb][0];
                __half2 l23 = *(__half2*)&accL[mb][nb][1];
                smf[rl * 132 + cl]           = accH[mb][nb][0] + __low2float(l01);
                smf[rl * 132 + cl + 1]       = accH[mb][nb][1] + __high2float(l01);
                smf[(rl + 8) * 132 + cl]     = accH[mb][nb][2] + __low2float(l23);
                smf[(rl + 8) * 132 + cl + 1] = accH[mb][nb][3] + __high2float(l23);
            }
        }
        __syncthreads();
        for (int i = tid; i < 128 * 64; i += 256) {
            int r = i >> 6, c = i & 63;
            float v1 = smf[r * 132 + c];
            float v2 = smf[r * 132 + c + 64];
            float s = v1 / (1.0f + __expf(-v1)) * v2;
            size_t o = (size_t)(m0 + r) * FF + (size_t)blockIdx.y * 64 + c;
            __half hv = __float2half(s);
            oh[o] = hv;
            ol[o] = __float2half(s - __half2float(hv));
        }
    }
}

// ======================= host driver =======================
extern "C" void kernel_launch(void* const* d_in, const int* in_sizes, int n_in,
                              void* d_out, int out_size) {
    const int*   ids = (const int*)  d_in[0];
    const float* emb = (const float*)d_in[1];
    const float* Wq  = (const float*)d_in[2];
    const float* Wk  = (const float*)d_in[3];
    const float* Wv  = (const float*)d_in[4];
    const float* Wo  = (const float*)d_in[5];
    const float* W1  = (const float*)d_in[6];
    const float* W2  = (const float*)d_in[7];
    const float* W3  = (const float*)d_in[8];
    const float* n1  = (const float*)d_in[9];
    const float* n2  = (const float*)d_in[10];
    const float* n3  = (const float*)d_in[11];
    const float* n4  = (const float*)d_in[12];
    const float* qn  = (const float*)d_in[13];
    const float* kn  = (const float*)d_in[14];
    const float* nf  = (const float*)d_in[15];
    const float* cosb = (const float*)d_in[16];
    const float* sinb = (const float*)d_in[17];
    float* out = (float*)d_out;

    float *x, *qkv, *t;
    cudaGetSymbolAddress((void**)&x,   g_x);
    cudaGetSymbolAddress((void**)&qkv, g_qkv);
    cudaGetSymbolAddress((void**)&t,   g_t);

    __half *ah, *al, *bh, *bl, *wqkv, *wo, *w12, *w3, *eh;
    cudaGetSymbolAddress((void**)&ah,   g_a_h);
    cudaGetSymbolAddress((void**)&al,   g_a_l);
    cudaGetSymbolAddress((void**)&bh,   g_b_h);
    cudaGetSymbolAddress((void**)&bl,   g_b_l);
    cudaGetSymbolAddress((void**)&wqkv, g_wqkv);
    cudaGetSymbolAddress((void**)&wo,   g_wot);
    cudaGetSymbolAddress((void**)&w12,  g_w12);
    cudaGetSymbolAddress((void**)&w3,   g_w3t);
    cudaGetSymbolAddress((void**)&eh,   g_emb);

    cudaFuncSetAttribute(gemm_fp16<1>, cudaFuncAttributeMaxDynamicSharedMemorySize, GSMEM);
    cudaFuncSetAttribute(gemm_fp16<0>, cudaFuncAttributeMaxDynamicSharedMemorySize, GSMEM);

    const int MT = NTOK / 128;
    dim3 wb(32, 8);

    // launches 1-3: minimal deps of layer-0 QKV GEMM; launch 4 = GEMM (ncu target)
    embed_kernel<<<NTOK, 256>>>(ids, emb, x);
    rmsnorm_split_kernel<<<NTOK, 256>>>(x, n1, ah, al);
    wconv_qkv_kernel<<<dim3(QKVW/32, 1024/32, NL), wb>>>(Wq, Wk, Wv, wqkv);
    gemm_fp16<1><<<dim3(MT, QKVW/128), 256, GSMEM>>>(ah, al, wqkv, qkv, nullptr, nullptr, QKVW, 1024, 0);

    // remaining weight conversions
    wconv_kernel<<<dim3(1024/32, 1024/32, NL), wb>>>(Wo, wo,  1024, 1024, (size_t)1024*1024, 0, 0);
    wconv_kernel<<<dim3(4096/32, 1024/32, NL), wb>>>(W1, w12, 1024, 4096, (size_t)F2W*1024, 0, 1);
    wconv_kernel<<<dim3(4096/32, 1024/32, NL), wb>>>(W2, w12, 1024, 4096, (size_t)F2W*1024, 0, 2);
    wconv_kernel<<<dim3(1024/32, 4096/32, NL), wb>>>(W3, w3,  4096, 1024, (size_t)4096*1024, 0, 0);
    half_kernel<<<(VOCAB*DIM)/256, 256>>>(emb, eh, VOCAB*DIM);

    for (int l = 0; l < NL; l++) {
        const int window = (l < NL - 4) ? WIN : 0;

        if (l > 0)
            gemm_fp16<1><<<dim3(MT, QKVW/128), 256, GSMEM>>>(ah, al,
                wqkv + (size_t)l*QKVW*1024, qkv, nullptr, nullptr, QKVW, 1024, 0);

        qkrope_kernel<<<dim3(NTOK, NH+NG), 64>>>(qkv, qn + (size_t)l * HDIM,
                                                 kn + (size_t)l * HDIM, cosb, sinb);

        flash_mma<<<dim3(SEQ/64, BATCH, NH), 128>>>(qkv, ah, al, window);

        gemm_fp16<1><<<dim3(MT, 1024/128), 256, GSMEM>>>(ah, al,
            wo + (size_t)l*1024*1024, t, nullptr, nullptr, 1024, 1024, 0);

        fuse_norm_kernel<<<NTOK, 256>>>(x, t, n2 + (size_t)l * DIM,
                                        n3 + (size_t)l * DIM, ah, al);

        gemm_fp16<1><<<dim3(MT, F2W/128), 256, GSMEM>>>(ah, al,
            w12 + (size_t)l*F2W*1024, nullptr, bh, bl, F2W, 1024, 1);

        gemm_fp16<1><<<dim3(MT, 1024/128), 256, GSMEM>>>(bh, bl,
            w3 + (size_t)l*1024*4096, t, nullptr, nullptr, 1024, 4096, 0);

        const float* so = (l < NL - 1) ? (n1 + (size_t)(l+1) * DIM) : nf;
        fuse_norm_kernel<<<NTOK, 256>>>(x, t, n4 + (size_t)l * DIM, so, ah, al);
    }

    // logits: 1-pass (A-lo dropped; error injected only at output, not compounded)
    gemm_fp16<0><<<dim3(MT, VOCAB/128), 256, GSMEM>>>(ah, nullptr, eh, out,
                                                      nullptr, nullptr, VOCAB, 1024, 0);
}

// round 15
// speedup vs baseline: 1.0567x; 1.0567x over previous
#include <cuda_runtime.h>
#include <cuda_fp16.h>
#include <math.h>
#include <stdint.h>

#define BATCH  2
#define SEQ    2048
#define DIM    1024
#define NH     16
#define NG     4
#define GRP    4
#define HDIM   64
#define FF     4096
#define NL     8
#define VOCAB  32000
#define WIN    1024
#define EPS    1e-6f
#define NTOK   (BATCH*SEQ)   // 4096
#define QKVW   1536
#define F2W    8192
#define INV2048 (1.0f/2048.0f)

// ======================= scratch =======================
__device__ float g_x   [NTOK*DIM];
__device__ float g_qkv [NTOK*QKVW];
__device__ float g_t   [NTOK*DIM];

__device__ __align__(128) __half g_a_h[NTOK*DIM];
__device__ __align__(128) __half g_a_l[NTOK*DIM];
__device__ __align__(128) __half g_b_h[NTOK*FF];
__device__ __align__(128) __half g_b_l[NTOK*FF];
__device__ __align__(128) __half g_k_h[NTOK*NG*HDIM];
__device__ __align__(128) __half g_k_l[NTOK*NG*HDIM];
__device__ __align__(128) __half g_v_h[NTOK*NG*HDIM];
__device__ __align__(128) __half g_v_l[NTOK*NG*HDIM];
__device__ __align__(128) __half g_wqkv[NL*QKVW*1024];
__device__ __align__(128) __half g_wot [NL*1024*1024];
__device__ __align__(128) __half g_w12 [NL*F2W*1024];
__device__ __align__(128) __half g_w3t [NL*1024*4096];
__device__ __align__(128) __half g_emb [VOCAB*DIM];

// ======================= small kernels =======================
__global__ void embed_kernel(const int* __restrict__ ids,
                             const float* __restrict__ emb,
                             float* __restrict__ x) {
    int t = blockIdx.x;
    int id = ids[t];
    const float* e = emb + (size_t)id * DIM;
    float* xp = x + (size_t)t * DIM;
    for (int d = threadIdx.x; d < DIM; d += blockDim.x)
        xp[d] = e[d] * 32.0f;
}

__global__ void half_kernel(const float* __restrict__ in,
                            __half* __restrict__ o, int n) {
    int i = blockIdx.x * 256 + threadIdx.x;
    if (i < n) o[i] = __float2half(in[i]);
}

// transpose to fp16 packed: W [L,K,N] fp32 -> out [L, prow(n), K]
__global__ void wconv_kernel(const float* __restrict__ W,
                             __half* __restrict__ o,
                             int K, int N, size_t lstride, int rowoff, int mode) {
    __shared__ float t[32][33];
    int l = blockIdx.z;
    const float* Wl = W + (size_t)l * K * N;
    size_t ob = (size_t)l * lstride;
    int n0 = blockIdx.x * 32, k0 = blockIdx.y * 32;
    int tx = threadIdx.x, ty = threadIdx.y;
#pragma unroll
    for (int r = 0; r < 32; r += 8)
        t[ty + r][tx] = Wl[(size_t)(k0 + ty + r) * N + n0 + tx];
    __syncthreads();
#pragma unroll
    for (int r = 0; r < 32; r += 8) {
        int n = n0 + ty + r;
        int prow;
        if (mode == 0)      prow = rowoff + n;
        else if (mode == 1) prow = ((n >> 6) << 7) + (n & 63);
        else                prow = ((n >> 6) << 7) + 64 + (n & 63);
        o[ob + (size_t)prow * K + k0 + tx] = __float2half(t[tx][ty + r]);
    }
}

// merged QKV weight conversion
__global__ void wconv_qkv_kernel(const float* __restrict__ Wq,
                                 const float* __restrict__ Wk,
                                 const float* __restrict__ Wv,
                                 __half* __restrict__ o) {
    __shared__ float t[32][33];
    int l = blockIdx.z;
    int n0 = blockIdx.x * 32, k0 = blockIdx.y * 32;
    int tx = threadIdx.x, ty = threadIdx.y;
    const float* W; int srcN, coff;
    if (n0 < 1024)      { W = Wq; srcN = 1024; coff = 0; }
    else if (n0 < 1280) { W = Wk; srcN = 256;  coff = 1024; }
    else                { W = Wv; srcN = 256;  coff = 1280; }
    const float* Wl = W + (size_t)l * 1024 * srcN;
    size_t ob = (size_t)l * QKVW * 1024;
#pragma unroll
    for (int r = 0; r < 32; r += 8)
        t[ty + r][tx] = Wl[(size_t)(k0 + ty + r) * srcN + (n0 - coff) + tx];
    __syncthreads();
#pragma unroll
    for (int r = 0; r < 32; r += 8)
        o[ob + (size_t)(n0 + ty + r) * 1024 + k0 + tx] = __float2half(t[tx][ty + r]);
}

__device__ __forceinline__ uint2 pack4h(float v0, float v1, float v2, float v3) {
    __half2 a = __halves2half2(__float2half(v0), __float2half(v1));
    __half2 b = __halves2half2(__float2half(v2), __float2half(v3));
    uint2 r;
    r.x = *(uint32_t*)&a;
    r.y = *(uint32_t*)&b;
    return r;
}

__global__ __launch_bounds__(256) void rmsnorm_split_kernel(const float* __restrict__ in,
                                                            const float* __restrict__ scale,
                                                            __half* __restrict__ oh,
                                                            __half* __restrict__ ol) {
    const int t = blockIdx.x;
    const int tid = threadIdx.x;
    float4 xv = ((const float4*)(in + (size_t)t * DIM))[tid];
    float ss = xv.x * xv.x + xv.y * xv.y + xv.z * xv.z + xv.w * xv.w;
    __shared__ float red[256];
    red[tid] = ss; __syncthreads();
    for (int o = 128; o > 0; o >>= 1) {
        if (tid < o) red[tid] += red[tid + o];
        __syncthreads();
    }
    const float r = rsqrtf(red[0] * (1.0f / DIM) + EPS);
    float4 sc = ((const float4*)scale)[tid];
    float v0 = xv.x * r * (1.0f + sc.x);
    float v1 = xv.y * r * (1.0f + sc.y);
    float v2 = xv.z * r * (1.0f + sc.z);
    float v3 = xv.w * r * (1.0f + sc.w);
    uint2 hh = pack4h(v0, v1, v2, v3);
    __half2* hp = (__half2*)&hh;
    float l0 = v0 - __low2float(hp[0]),  l1 = v1 - __high2float(hp[0]);
    float l2 = v2 - __low2float(hp[1]),  l3 = v3 - __high2float(hp[1]);
    ((uint2*)(oh + (size_t)t * DIM))[tid] = hh;
    ((uint2*)(ol + (size_t)t * DIM))[tid] = pack4h(l0, l1, l2, l3);
}

// x += rmsnorm(t, sa); then out = rmsnorm(x, so) -> split fp16 (vectorized)
__global__ __launch_bounds__(256) void fuse_norm_kernel(float* __restrict__ x,
                                                        const float* __restrict__ t,
                                                        const float* __restrict__ sa,
                                                        const float* __restrict__ so,
                                                        __half* __restrict__ oh,
                                                        __half* __restrict__ ol) {
    const int tk = blockIdx.x;
    const int tid = threadIdx.x;
    float4 tv = ((const float4*)(t + (size_t)tk * DIM))[tid];
    float ss = tv.x * tv.x + tv.y * tv.y + tv.z * tv.z + tv.w * tv.w;
    __shared__ float red[256];
    red[tid] = ss; __syncthreads();
    for (int o = 128; o > 0; o >>= 1) {
        if (tid < o) red[tid] += red[tid + o];
        __syncthreads();
    }
    const float r1 = rsqrtf(red[0] * (1.0f / DIM) + EPS);
    __syncthreads();
    float4 sa4 = ((const float4*)sa)[tid];
    float4* xp4 = (float4*)(x + (size_t)tk * DIM);
    float4 xv = xp4[tid];
    xv.x += tv.x * r1 * (1.0f + sa4.x);
    xv.y += tv.y * r1 * (1.0f + sa4.y);
    xv.z += tv.z * r1 * (1.0f + sa4.z);
    xv.w += tv.w * r1 * (1.0f + sa4.w);
    float ss2 = xv.x * xv.x + xv.y * xv.y + xv.z * xv.z + xv.w * xv.w;
    xp4[tid] = xv;
    red[tid] = ss2; __syncthreads();
    for (int o = 128; o > 0; o >>= 1) {
        if (tid < o) red[tid] += red[tid + o];
        __syncthreads();
    }
    const float r2 = rsqrtf(red[0] * (1.0f / DIM) + EPS);
    float4 so4 = ((const float4*)so)[tid];
    float v0 = xv.x * r2 * (1.0f + so4.x);
    float v1 = xv.y * r2 * (1.0f + so4.y);
    float v2 = xv.z * r2 * (1.0f + so4.z);
    float v3 = xv.w * r2 * (1.0f + so4.w);
    uint2 hh = pack4h(v0, v1, v2, v3);
    __half2* hp = (__half2*)&hh;
    float l0 = v0 - __low2float(hp[0]),  l1 = v1 - __high2float(hp[0]);
    float l2 = v2 - __low2float(hp[1]),  l3 = v3 - __high2float(hp[1]);
    ((uint2*)(oh + (size_t)tk * DIM))[tid] = hh;
    ((uint2*)(ol + (size_t)tk * DIM))[tid] = pack4h(l0, l1, l2, l3);
}

// merged q+k rmsnorm+rope + v convert: blockIdx.y in [0, NH+2*NG)
// q (hh<NH): norm+rope -> fp32 in qkv
// k (NH<=hh<NH+NG): norm+rope -> 2-limb fp16 buffers
// v (hh>=NH+NG): straight 2-limb fp16 convert
__global__ __launch_bounds__(64) void qkrope_kernel(float* __restrict__ x,
                                                    const float* __restrict__ qsc,
                                                    const float* __restrict__ ksc,
                                                    const float* __restrict__ cosb,
                                                    const float* __restrict__ sinb,
                                                    __half* __restrict__ kh, __half* __restrict__ kl,
                                                    __half* __restrict__ vh, __half* __restrict__ vl) {
    const int token = blockIdx.x;
    const int hh = blockIdx.y;
    const int pos = token % SEQ;
    const int d = threadIdx.x;

    if (hh >= NH + NG) {   // V: no norm, no rope — just 2-limb convert
        const int g = hh - NH - NG;
        float v = x[(size_t)token * QKVW + 1280 + g * HDIM + d];
        __half h = __float2half(v);
        size_t o = ((size_t)token * NG + g) * HDIM + d;
        vh[o] = h;
        vl[o] = __float2half((v - __half2float(h)) * 2048.0f);
        return;
    }

    const float* scale = (hh < NH) ? qsc : ksc;
    const int off = (hh < NH) ? hh * HDIM : 1024 + (hh - NH) * HDIM;
    float* xp = x + (size_t)token * QKVW + off;
    const float val = xp[d];
    __shared__ float sh[HDIM];
    sh[d] = val * val;
    __syncthreads();
    for (int o = 32; o > 0; o >>= 1) {
        if (d < o) sh[d] += sh[d + o];
        __syncthreads();
    }
    const float r = rsqrtf(sh[0] * (1.0f / HDIM) + EPS);
    __syncthreads();
    const float nv = val * r * (1.0f + scale[d]);
    sh[d] = nv;
    __syncthreads();
    const float rot = (d < 32) ? -sh[d + 32] : sh[d - 32];
    const float out = nv * cosb[pos * HDIM + d] + rot * sinb[pos * HDIM + d];
    if (hh < NH) {
        xp[d] = out;
    } else {
        const int g = hh - NH;
        __half h = __float2half(out);
        size_t o = ((size_t)token * NG + g) * HDIM + d;
        kh[o] = h;
        kl[o] = __float2half((out - __half2float(h)) * 2048.0f);
    }
}

// ======================= mma helpers =======================
__device__ __forceinline__ uint32_t smem_u32(const void* p) {
    uint32_t a;
    asm("{ .reg .u64 t; cvta.to.shared.u64 t, %1; cvt.u32.u64 %0, t; }" : "=r"(a) : "l"(p));
    return a;
}
__device__ __forceinline__ void cp16(uint32_t s, const void* g) {
    asm volatile("cp.async.cg.shared.global [%0], [%1], 16;" :: "r"(s), "l"(g));
}
#define LDMX4(r0, r1, r2, r3, addr) \
    asm volatile("ldmatrix.sync.aligned.m8n8.x4.shared.b16 {%0,%1,%2,%3}, [%4];" \
        : "=r"(r0), "=r"(r1), "=r"(r2), "=r"(r3) : "r"(addr))
#define LDMX4T(r0, r1, r2, r3, addr) \
    asm volatile("ldmatrix.sync.aligned.m8n8.x4.trans.shared.b16 {%0,%1,%2,%3}, [%4];" \
        : "=r"(r0), "=r"(r1), "=r"(r2), "=r"(r3) : "r"(addr))
#define MMA16816(d, a, b) \
    asm volatile("mma.sync.aligned.m16n8k16.row.col.f32.f16.f16.f32 " \
        "{%0,%1,%2,%3}, {%4,%5,%6,%7}, {%8,%9}, {%0,%1,%2,%3};" \
        : "+f"((d)[0]), "+f"((d)[1]), "+f"((d)[2]), "+f"((d)[3]) \
        : "r"((a)[0]), "r"((a)[1]), "r"((a)[2]), "r"((a)[3]), "r"((b)[0]), "r"((b)[1]))
#define MMA16816H(d, a, b) \
    asm volatile("mma.sync.aligned.m16n8k16.row.col.f16.f16.f16.f16 " \
        "{%0,%1}, {%2,%3,%4,%5}, {%6,%7}, {%0,%1};" \
        : "+r"((d)[0]), "+r"((d)[1]) \
        : "r"((a)[0]), "r"((a)[1]), "r"((a)[2]), "r"((a)[3]), "r"((b)[0]), "r"((b)[1]))

// ======================= flash attention (tensor core, 2-limb fp16) =======================
#define FSW(r, u) ((r)*128 + (((u) ^ ((r)&7)) << 4))

__device__ __forceinline__ void fa_cvt_store(char* hbuf, char* lbuf, int r, int u,
                                             const float* src, float scale) {
    float4 f0 = *(const float4*)src;
    float4 f1 = *(const float4*)(src + 4);
    float v[8] = {f0.x, f0.y, f0.z, f0.w, f1.x, f1.y, f1.z, f1.w};
    __half hv[8], lv[8];
#pragma unroll
    for (int i = 0; i < 8; i++) {
        float x = v[i] * scale;
        __half hh = __float2half(x);
        hv[i] = hh;
        lv[i] = __float2half((x - __half2float(hh)) * 2048.0f);
    }
    uint32_t off = FSW(r, u);
    *(uint4*)(hbuf + off) = *(uint4*)hv;
    *(uint4*)(lbuf + off) = *(uint4*)lv;
}

__global__ __launch_bounds__(128) void flash_mma(const float* __restrict__ qkv,
                                                 const __half* __restrict__ kh,
                                                 const __half* __restrict__ kl,
                                                 const __half* __restrict__ vh,
                                                 const __half* __restrict__ vl,
                                                 __half* __restrict__ oh,
                                                 __half* __restrict__ ol,
                                                 int window) {
    __shared__ __align__(128) char sm[32768];
    char* khb = sm;
    char* klb = sm + 8192;
    char* vhb = sm + 16384;
    char* vlb = sm + 24576;
    const uint32_t khs = smem_u32(khb);
    const uint32_t kls = khs + 8192;
    const uint32_t vhs = khs + 16384;
    const uint32_t vls = khs + 24576;

    const int qt = blockIdx.x, b = blockIdx.y, h = blockIdx.z;
    const int g = h / GRP;
    const int tid = threadIdx.x;
    const int w = tid >> 5, lane = tid & 31;
    const int q0 = qt * 64;

    // Q tile: fp32 -> 2-limb (once per block), staged through kh smem
    for (int task = tid; task < 512; task += 128) {
        int r = task >> 3, u = task & 7;
        fa_cvt_store(khb, klb, r, u,
                     qkv + (size_t)(b * SEQ + q0 + r) * QKVW + h * HDIM + u * 8, 0.125f);
    }
    __syncthreads();
    uint32_t qfh[4][4], qfl[4][4];
    {
        int row = w * 16 + (lane & 15);
#pragma unroll
        for (int ks = 0; ks < 4; ks++) {
            int u = ks * 2 + (lane >> 4);
            LDMX4(qfh[ks][0], qfh[ks][1], qfh[ks][2], qfh[ks][3], khs + FSW(row, u));
            LDMX4(qfl[ks][0], qfl[ks][1], qfl[ks][2], qfl[ks][3], kls + FSW(row, u));
        }
    }

    float accH[8][4] = {}, accL[8][4] = {};
    float mrun0 = -1e30f, mrun1 = -1e30f, srun0 = 0.f, srun1 = 0.f;

    const int i0 = q0 + w * 16 + (lane >> 2);
    const int i1 = i0 + 8;

    int t0 = 0;
    if (window > 0) { int lo = q0 - window; if (lo > 0) t0 = lo >> 6; }

    for (int kt = t0; kt <= qt; kt++) {
        const int k0 = kt * 64;
        __syncthreads();
        // pure copy: precomputed 2-limb fp16 K/V -> swizzled smem
        for (int task = tid; task < 512; task += 128) {
            int r = task >> 3, u = task & 7;
            size_t base = ((size_t)(b * SEQ + k0 + r) * NG + g) * HDIM + u * 8;
            uint32_t off = FSW(r, u);
            *(uint4*)(khb + off) = *(const uint4*)(kh + base);
            *(uint4*)(klb + off) = *(const uint4*)(kl + base);
            *(uint4*)(vhb + off) = *(const uint4*)(vh + base);
            *(uint4*)(vlb + off) = *(const uint4*)(vl + base);
        }
        __syncthreads();

        float sH[8][4] = {}, sL[8][4] = {};
#pragma unroll
        for (int ks = 0; ks < 4; ks++) {
            const int bm = lane >> 3;
            const int brow = ((bm >> 1) << 3) + (lane & 7);
            const int bu = ks * 2 + (bm & 1);
#pragma unroll
            for (int p2 = 0; p2 < 4; p2++) {
                uint32_t bh[2][2], bl[2][2];
                uint32_t t0r, t1r, t2r, t3r;
                LDMX4(t0r, t1r, t2r, t3r, khs + FSW(p2 * 16 + brow, bu));
                bh[0][0] = t0r; bh[0][1] = t1r; bh[1][0] = t2r; bh[1][1] = t3r;
                LDMX4(t0r, t1r, t2r, t3r, kls + FSW(p2 * 16 + brow, bu));
                bl[0][0] = t0r; bl[0][1] = t1r; bl[1][0] = t2r; bl[1][1] = t3r;
#pragma unroll
                for (int q2 = 0; q2 < 2; q2++) {
                    int nt = p2 * 2 + q2;
                    MMA16816(sH[nt], qfh[ks], bh[q2]);
                    MMA16816(sL[nt], qfl[ks], bh[q2]);
                    MMA16816(sL[nt], qfh[ks], bl[q2]);
                }
            }
        }

        float mt0 = -1e30f, mt1 = -1e30f;
#pragma unroll
        for (int nt = 0; nt < 8; nt++) {
            int j0 = k0 + nt * 8 + 2 * (lane & 3);
            int j1 = j0 + 1;
            bool v00 = (j0 <= i0) && (window == 0 || i0 - j0 <= window);
            bool v01 = (j1 <= i0) && (window == 0 || i0 - j1 <= window);
            bool v10 = (j0 <= i1) && (window == 0 || i1 - j0 <= window);
            bool v11 = (j1 <= i1) && (window == 0 || i1 - j1 <= window);
            sH[nt][0] = v00 ? sH[nt][0] + sL[nt][0] * INV2048 : -1e30f;
            sH[nt][1] = v01 ? sH[nt][1] + sL[nt][1] * INV2048 : -1e30f;
            sH[nt][2] = v10 ? sH[nt][2] + sL[nt][2] * INV2048 : -1e30f;
            sH[nt][3] = v11 ? sH[nt][3] + sL[nt][3] * INV2048 : -1e30f;
            mt0 = fmaxf(mt0, fmaxf(sH[nt][0], sH[nt][1]));
            mt1 = fmaxf(mt1, fmaxf(sH[nt][2], sH[nt][3]));
        }
        mt0 = fmaxf(mt0, __shfl_xor_sync(0xffffffffu, mt0, 1));
        mt0 = fmaxf(mt0, __shfl_xor_sync(0xffffffffu, mt0, 2));
        mt1 = fmaxf(mt1, __shfl_xor_sync(0xffffffffu, mt1, 1));
        mt1 = fmaxf(mt1, __shfl_xor_sync(0xffffffffu, mt1, 2));

        const float mn0 = fmaxf(mrun0, mt0);
        const float mn1 = fmaxf(mrun1, mt1);
        const float al0 = __expf(mrun0 - mn0);
        const float al1 = __expf(mrun1 - mn1);
        mrun0 = mn0; mrun1 = mn1;

        float rs0 = 0.f, rs1 = 0.f;
#pragma unroll
        for (int nt = 0; nt < 8; nt++) {
            sH[nt][0] = __expf(sH[nt][0] - mn0);
            sH[nt][1] = __expf(sH[nt][1] - mn0);
            sH[nt][2] = __expf(sH[nt][2] - mn1);
            sH[nt][3] = __expf(sH[nt][3] - mn1);
            rs0 += sH[nt][0] + sH[nt][1];
            rs1 += sH[nt][2] + sH[nt][3];
        }
        rs0 += __shfl_xor_sync(0xffffffffu, rs0, 1);
        rs0 += __shfl_xor_sync(0xffffffffu, rs0, 2);
        rs1 += __shfl_xor_sync(0xffffffffu, rs1, 1);
        rs1 += __shfl_xor_sync(0xffffffffu, rs1, 2);
        srun0 = srun0 * al0 + rs0;
        srun1 = srun1 * al1 + rs1;

#pragma unroll
        for (int nt = 0; nt < 8; nt++) {
            accH[nt][0] *= al0; accH[nt][1] *= al0; accH[nt][2] *= al1; accH[nt][3] *= al1;
            accL[nt][0] *= al0; accL[nt][1] *= al0; accL[nt][2] *= al1; accL[nt][3] *= al1;
        }

        uint32_t pah[4][4], pal[4][4];
#pragma unroll
        for (int j = 0; j < 4; j++) {
#pragma unroll
            for (int q2 = 0; q2 < 2; q2++) {
                int nt = 2 * j + q2;
#pragma unroll
                for (int half_ = 0; half_ < 2; half_++) {
                    float p0 = sH[nt][half_ * 2 + 0];
                    float p1 = sH[nt][half_ * 2 + 1];
                    __half h0 = __float2half(p0), h1 = __float2half(p1);
                    __half l0 = __float2half((p0 - __half2float(h0)) * 2048.0f);
                    __half l1 = __float2half((p1 - __half2float(h1)) * 2048.0f);
                    __half2 hp = __halves2half2(h0, h1);
                    __half2 lp = __halves2half2(l0, l1);
                    pah[j][q2 * 2 + half_] = *(uint32_t*)&hp;
                    pal[j][q2 * 2 + half_] = *(uint32_t*)&lp;
                }
            }
        }

        {
            const int vrow_base = ((lane >> 3) & 1) * 8 + (lane & 7);
            const int vu_add = lane >> 4;
#pragma unroll
            for (int ks = 0; ks < 4; ks++) {
#pragma unroll
                for (int d2 = 0; d2 < 4; d2++) {
                    int row = ks * 16 + vrow_base;
                    int u = 2 * d2 + vu_add;
                    uint32_t t0r, t1r, t2r, t3r;
                    uint32_t vbh[2][2], vbl[2][2];
                    LDMX4T(t0r, t1r, t2r, t3r, vhs + FSW(row, u));
                    vbh[0][0] = t0r; vbh[0][1] = t1r; vbh[1][0] = t2r; vbh[1][1] = t3r;
                    LDMX4T(t0r, t1r, t2r, t3r, vls + FSW(row, u));
                    vbl[0][0] = t0r; vbl[0][1] = t1r; vbl[1][0] = t2r; vbl[1][1] = t3r;
#pragma unroll
                    for (int dd = 0; dd < 2; dd++) {
                        int nt = 2 * d2 + dd;
                        MMA16816(accH[nt], pah[ks], vbh[dd]);
                        MMA16816(accL[nt], pal[ks], vbh[dd]);
                        MMA16816(accL[nt], pah[ks], vbl[dd]);
                    }
                }
            }
        }
    }

    const float inv0 = 1.0f / srun0;
    const float inv1 = 1.0f / srun1;
    const size_t tok0 = (size_t)(b * SEQ) + q0 + w * 16 + (lane >> 2);
    const size_t tok1 = tok0 + 8;
#pragma unroll
    for (int nt = 0; nt < 8; nt++) {
        int col = h * HDIM + nt * 8 + 2 * (lane & 3);
        float o00 = (accH[nt][0] + accL[nt][0] * INV2048) * inv0;
        float o01 = (accH[nt][1] + accL[nt][1] * INV2048) * inv0;
        float o10 = (accH[nt][2] + accL[nt][2] * INV2048) * inv1;
        float o11 = (accH[nt][3] + accL[nt][3] * INV2048) * inv1;
        __half h00 = __float2half(o00), h01 = __float2half(o01);
        __half h10 = __float2half(o10), h11 = __float2half(o11);
        __half2 hi0 = __halves2half2(h00, h01);
        __half2 hi1 = __halves2half2(h10, h11);
        __half2 lo0 = __halves2half2(__float2half(o00 - __half2float(h00)),
                                     __float2half(o01 - __half2float(h01)));
        __half2 lo1 = __halves2half2(__float2half(o10 - __half2float(h10)),
                                     __float2half(o11 - __half2float(h11)));
        *(__half2*)(oh + tok0 * DIM + col) = hi0;
        *(__half2*)(ol + tok0 * DIM + col) = lo0;
        *(__half2*)(oh + tok1 * DIM + col) = hi1;
        *(__half2*)(ol + tok1 * DIM + col) = lo1;
    }
}

// ======================= fp16 GEMM (r13 proven: 4-stage, dual frag, 1 CTA/SM) =======================
#define SSTG      24576
#define NSTAGE    4
#define GSMEM     (NSTAGE*SSTG)   // 96 KB

struct Frag {
    uint32_t a[2][2][4];
    uint32_t b[8][2];
};

template<int TP>
__device__ __forceinline__ void load_frags(Frag& f, uint32_t st, int ks,
                                           int a_r, int a_uadd, int b_r0, int b_uadd) {
#pragma unroll
    for (int mb = 0; mb < 2; mb++) {
        int r = a_r + mb * 16;
        int u = ks * 2 + a_uadd;
        uint32_t off = r * 64 + ((u ^ ((r >> 1) & 3)) << 4);
        LDMX4(f.a[0][mb][0], f.a[0][mb][1], f.a[0][mb][2], f.a[0][mb][3], st + off);
        if (TP)
            LDMX4(f.a[1][mb][0], f.a[1][mb][1], f.a[1][mb][2], f.a[1][mb][3], st + 8192 + off);
    }
#pragma unroll
    for (int qd = 0; qd < 4; qd++) {
        int r = b_r0 + qd * 16;
        int u = ks * 2 + b_uadd;
        uint32_t off = r * 64 + ((u ^ ((r >> 1) & 3)) << 4);
        uint32_t t0, t1, t2, t3;
        LDMX4(t0, t1, t2, t3, st + 16384 + off);
        f.b[2*qd][0] = t0; f.b[2*qd][1] = t1;
        f.b[2*qd+1][0] = t2; f.b[2*qd+1][1] = t3;
    }
}

template<int TP>
__device__ __forceinline__ void do_mma(float accH[2][8][4], uint32_t accL[2][8][2],
                                       const Frag& f) {
#pragma unroll
    for (int mb = 0; mb < 2; mb++)
#pragma unroll
        for (int nb = 0; nb < 8; nb++) {
            MMA16816(accH[mb][nb], f.a[0][mb], f.b[nb]);
            if (TP)
                MMA16816H(accL[mb][nb], f.a[1][mb], f.b[nb]);
        }
}

template<int TP>
__device__ __forceinline__ void stage_load(uint32_t st,
                                           const __half* Ah, const __half* Al,
                                           const __half* Bh,
                                           int m0, int n0, int k0, int K, int tid) {
#pragma unroll
    for (int c = tid; c < 512; c += 256) {
        int r = c >> 2, u = c & 3;
        uint32_t off = r * 64 + ((u ^ ((r >> 1) & 3)) << 4);
        size_t ga = (size_t)(m0 + r) * K + k0 + u * 8;
        size_t gb = (size_t)(n0 + r) * K + k0 + u * 8;
        cp16(st + off,          Ah + ga);
        if (TP)
            cp16(st + 8192 + off, Al + ga);
        cp16(st + 16384 + off,  Bh + gb);
    }
    asm volatile("cp.async.commit_group;" ::: "memory");
}

template<int TP>
__global__ __launch_bounds__(256) void gemm_fp16(
    const __half* __restrict__ Ah, const __half* __restrict__ Al,
    const __half* __restrict__ Bh,
    float* __restrict__ C, __half* __restrict__ oh, __half* __restrict__ ol,
    int N, int K, int silu)
{
    extern __shared__ __align__(128) char smem[];
    const uint32_t sb = smem_u32(smem);
    const int tid = threadIdx.x;
    const int lane = tid & 31;
    const int w = tid >> 5;
    const int wm = w & 3;
    const int wn = w >> 2;
    const int m0 = blockIdx.x * 128;
    const int n0 = blockIdx.y * 128;
    const int niter = K >> 5;

    float accH[2][8][4] = {};
    uint32_t accL[2][8][2] = {};
    Frag f0, f1;

    stage_load<TP>(sb + 0*SSTG, Ah, Al, Bh, m0, n0, 0,  K, tid);
    stage_load<TP>(sb + 1*SSTG, Ah, Al, Bh, m0, n0, 32, K, tid);
    stage_load<TP>(sb + 2*SSTG, Ah, Al, Bh, m0, n0, 64, K, tid);

    const int a_r = wm * 32 + (lane & 15);
    const int a_uadd = lane >> 4;
    const int b_mat = lane >> 3;
    const int b_r0 = wn * 64 + ((b_mat >> 1) << 3) + (lane & 7);
    const int b_uadd = b_mat & 1;

    asm volatile("cp.async.wait_group 1;" ::: "memory");
    __syncthreads();
    load_frags<TP>(f0, sb, 0, a_r, a_uadd, b_r0, b_uadd);

    for (int it = 0; it < niter; it++) {
        const uint32_t st  = sb + (it & 3) * SSTG;
        const uint32_t stn = sb + ((it + 1) & 3) * SSTG;

        load_frags<TP>(f1, st, 1, a_r, a_uadd, b_r0, b_uadd);
        do_mma<TP>(accH, accL, f0);
        if (it + 1 < niter)
            load_frags<TP>(f0, stn, 0, a_r, a_uadd, b_r0, b_uadd);
        do_mma<TP>(accH, accL, f1);

        if ((it + 3) * 32 < K) {
            stage_load<TP>(sb + ((it + 3) & 3) * SSTG, Ah, Al, Bh, m0, n0, (it + 3) * 32, K, tid);
            asm volatile("cp.async.wait_group 1;" ::: "memory");
        } else {
            asm volatile("cp.async.wait_group 0;" ::: "memory");
        }
        __syncthreads();
    }

    if (!silu) {
#pragma unroll
        for (int mb = 0; mb < 2; mb++) {
            int row = m0 + wm * 32 + mb * 16 + (lane >> 2);
#pragma unroll
            for (int nb = 0; nb < 8; nb++) {
                int col = n0 + wn * 64 + nb * 8 + 2 * (lane & 3);
                float c0 = accH[mb][nb][0];
                float c1 = accH[mb][nb][1];
                float c2 = accH[mb][nb][2];
                float c3 = accH[mb][nb][3];
                if (TP) {
                    __half2 l01 = *(__half2*)&accL[mb][nb][0];
                    __half2 l23 = *(__half2*)&accL[mb][nb][1];
                    c0 += __low2float(l01);  c1 += __high2float(l01);
                    c2 += __low2float(l23);  c3 += __high2float(l23);
                }
                *(float2*)(C + (size_t)row * N + col)       = make_float2(c0, c1);
                *(float2*)(C + (size_t)(row + 8) * N + col) = make_float2(c2, c3);
            }
        }
    } else {
        float* smf = (float*)smem;
#pragma unroll
        for (int mb = 0; mb < 2; mb++) {
            int rl = wm * 32 + mb * 16 + (lane >> 2);
#pragma unroll
            for (int nb = 0; nb < 8; nb++) {
                int cl = wn * 64 + nb * 8 + 2 * (lane & 3);
                __half2 l01 = *(__half2*)&accL[mb][nb][0];
                __half2 l23 = *(__half2*)&accL[mb][nb][1];
                smf[rl * 132 + cl]           = accH[mb][nb][0] + __low2float(l01);
                smf[rl * 132 + cl + 1]       = accH[mb][nb][1] + __high2float(l01);
                smf[(rl + 8) * 132 + cl]     = accH[mb][nb][2] + __low2float(l23);
                smf[(rl + 8) * 132 + cl + 1] = accH[mb][nb][3] + __high2float(l23);
            }
        }
        __syncthreads();
        for (int i = tid; i < 128 * 64; i += 256) {
            int r = i >> 6, c = i & 63;
            float v1 = smf[r * 132 + c];
            float v2 = smf[r * 132 + c + 64];
            float s = v1 / (1.0f + __expf(-v1)) * v2;
            size_t o = (size_t)(m0 + r) * FF + (size_t)blockIdx.y * 64 + c;
            __half hv = __float2half(s);
            oh[o] = hv;
            ol[o] = __float2half(s - __half2float(hv));
        }
    }
}

// ======================= host driver =======================
extern "C" void kernel_launch(void* const* d_in, const int* in_sizes, int n_in,
                              void* d_out, int out_size) {
    const int*   ids = (const int*)  d_in[0];
    const float* emb = (const float*)d_in[1];
    const float* Wq  = (const float*)d_in[2];
    const float* Wk  = (const float*)d_in[3];
    const float* Wv  = (const float*)d_in[4];
    const float* Wo  = (const float*)d_in[5];
    const float* W1  = (const float*)d_in[6];
    const float* W2  = (const float*)d_in[7];
    const float* W3  = (const float*)d_in[8];
    const float* n1  = (const float*)d_in[9];
    const float* n2  = (const float*)d_in[10];
    const float* n3  = (const float*)d_in[11];
    const float* n4  = (const float*)d_in[12];
    const float* qn  = (const float*)d_in[13];
    const float* kn  = (const float*)d_in[14];
    const float* nf  = (const float*)d_in[15];
    const float* cosb = (const float*)d_in[16];
    const float* sinb = (const float*)d_in[17];
    float* out = (float*)d_out;

    float *x, *qkv, *t;
    cudaGetSymbolAddress((void**)&x,   g_x);
    cudaGetSymbolAddress((void**)&qkv, g_qkv);
    cudaGetSymbolAddress((void**)&t,   g_t);

    __half *ah, *al, *bh, *bl, *kh, *kl, *vh, *vl, *wqkv, *wo, *w12, *w3, *eh;
    cudaGetSymbolAddress((void**)&ah,   g_a_h);
    cudaGetSymbolAddress((void**)&al,   g_a_l);
    cudaGetSymbolAddress((void**)&bh,   g_b_h);
    cudaGetSymbolAddress((void**)&bl,   g_b_l);
    cudaGetSymbolAddress((void**)&kh,   g_k_h);
    cudaGetSymbolAddress((void**)&kl,   g_k_l);
    cudaGetSymbolAddress((void**)&vh,   g_v_h);
    cudaGetSymbolAddress((void**)&vl,   g_v_l);
    cudaGetSymbolAddress((void**)&wqkv, g_wqkv);
    cudaGetSymbolAddress((void**)&wo,   g_wot);
    cudaGetSymbolAddress((void**)&w12,  g_w12);
    cudaGetSymbolAddress((void**)&w3,   g_w3t);
    cudaGetSymbolAddress((void**)&eh,   g_emb);

    cudaFuncSetAttribute(gemm_fp16<1>, cudaFuncAttributeMaxDynamicSharedMemorySize, GSMEM);
    cudaFuncSetAttribute(gemm_fp16<0>, cudaFuncAttributeMaxDynamicSharedMemorySize, GSMEM);

    const int MT = NTOK / 128;
    dim3 wb(32, 8);

    // launches 1-3: minimal deps of layer-0 QKV GEMM; launch 4 = GEMM (ncu target)
    embed_kernel<<<NTOK, 256>>>(ids, emb, x);
    rmsnorm_split_kernel<<<NTOK, 256>>>(x, n1, ah, al);
    wconv_qkv_kernel<<<dim3(QKVW/32, 1024/32, NL), wb>>>(Wq, Wk, Wv, wqkv);
    gemm_fp16<1><<<dim3(MT, QKVW/128), 256, GSMEM>>>(ah, al, wqkv, qkv, nullptr, nullptr, QKVW, 1024, 0);

    // remaining weight conversions
    wconv_kernel<<<dim3(1024/32, 1024/32, NL), wb>>>(Wo, wo,  1024, 1024, (size_t)1024*1024, 0, 0);
    wconv_kernel<<<dim3(4096/32, 1024/32, NL), wb>>>(W1, w12, 1024, 4096, (size_t)F2W*1024, 0, 1);
    wconv_kernel<<<dim3(4096/32, 1024/32, NL), wb>>>(W2, w12, 1024, 4096, (size_t)F2W*1024, 0, 2);
    wconv_kernel<<<dim3(1024/32, 4096/32, NL), wb>>>(W3, w3,  4096, 1024, (size_t)4096*1024, 0, 0);
    half_kernel<<<(VOCAB*DIM)/256, 256>>>(emb, eh, VOCAB*DIM);

    for (int l = 0; l < NL; l++) {
        const int window = (l < NL - 4) ? WIN : 0;

        if (l > 0)
            gemm_fp16<1><<<dim3(MT, QKVW/128), 256, GSMEM>>>(ah, al,
                wqkv + (size_t)l*QKVW*1024, qkv, nullptr, nullptr, QKVW, 1024, 0);

        qkrope_kernel<<<dim3(NTOK, NH + 2*NG), 64>>>(qkv, qn + (size_t)l * HDIM,
                                                     kn + (size_t)l * HDIM, cosb, sinb,
                                                     kh, kl, vh, vl);

        flash_mma<<<dim3(SEQ/64, BATCH, NH), 128>>>(qkv, kh, kl, vh, vl, ah, al, window);

        gemm_fp16<1><<<dim3(MT, 1024/128), 256, GSMEM>>>(ah, al,
            wo + (size_t)l*1024*1024, t, nullptr, nullptr, 1024, 1024, 0);

        fuse_norm_kernel<<<NTOK, 256>>>(x, t, n2 + (size_t)l * DIM,
                                        n3 + (size_t)l * DIM, ah, al);

        gemm_fp16<1><<<dim3(MT, F2W/128), 256, GSMEM>>>(ah, al,
            w12 + (size_t)l*F2W*1024, nullptr, bh, bl, F2W, 1024, 1);

        gemm_fp16<1><<<dim3(MT, 1024/128), 256, GSMEM>>>(bh, bl,
            w3 + (size_t)l*1024*4096, t, nullptr, nullptr, 1024, 4096, 0);

        const float* so = (l < NL - 1) ? (n1 + (size_t)(l+1) * DIM) : nf;
        fuse_norm_kernel<<<NTOK, 256>>>(x, t, n4 + (size_t)l * DIM, so, ah, al);
    }

    // logits: 1-pass (A-lo dropped; error injected only at output, not compounded)
    gemm_fp16<0><<<dim3(MT, VOCAB/128), 256, GSMEM>>>(ah, nullptr, eh, out,
                                                      nullptr, nullptr, VOCAB, 1024, 0);
}

// round 16
// speedup vs baseline: 1.0800x; 1.0220x over previous
#include <cuda_runtime.h>
#include <cuda_fp16.h>
#include <math.h>
#include <stdint.h>

#define BATCH  2
#define SEQ    2048
#define DIM    1024
#define NH     16
#define NG     4
#define GRP    4
#define HDIM   64
#define FF     4096
#define NL     8
#define VOCAB  32000
#define WIN    1024
#define EPS    1e-6f
#define NTOK   (BATCH*SEQ)   // 4096
#define QKVW   1536
#define F2W    8192
#define INV2048 (1.0f/2048.0f)

// ======================= scratch =======================
__device__ float g_x   [NTOK*DIM];
__device__ float g_qkv [NTOK*QKVW];
__device__ float g_t   [NTOK*DIM];

__device__ __align__(128) __half g_a_h[NTOK*DIM];
__device__ __align__(128) __half g_a_l[NTOK*DIM];
__device__ __align__(128) __half g_b_h[NTOK*FF];
__device__ __align__(128) __half g_b_l[NTOK*FF];
__device__ __align__(128) __half g_k_h[NTOK*NG*HDIM];
__device__ __align__(128) __half g_k_l[NTOK*NG*HDIM];
__device__ __align__(128) __half g_v_h[NTOK*NG*HDIM];
__device__ __align__(128) __half g_v_l[NTOK*NG*HDIM];
__device__ __align__(128) __half g_wqkv[NL*QKVW*1024];
__device__ __align__(128) __half g_wot [NL*1024*1024];
__device__ __align__(128) __half g_w12 [NL*F2W*1024];
__device__ __align__(128) __half g_w3t [NL*1024*4096];
__device__ __align__(128) __half g_emb [VOCAB*DIM];

// ======================= small kernels =======================
__global__ void embed_kernel(const int* __restrict__ ids,
                             const float* __restrict__ emb,
                             float* __restrict__ x) {
    int t = blockIdx.x;
    int id = ids[t];
    const float* e = emb + (size_t)id * DIM;
    float* xp = x + (size_t)t * DIM;
    for (int d = threadIdx.x; d < DIM; d += blockDim.x)
        xp[d] = e[d] * 32.0f;
}

__global__ void half_kernel(const float* __restrict__ in,
                            __half* __restrict__ o, int n) {
    int i = blockIdx.x * 256 + threadIdx.x;
    if (i < n) o[i] = __float2half(in[i]);
}

// transpose to fp16 packed: W [L,K,N] fp32 -> out [L, prow(n), K]
__global__ void wconv_kernel(const float* __restrict__ W,
                             __half* __restrict__ o,
                             int K, int N, size_t lstride, int rowoff, int mode) {
    __shared__ float t[32][33];
    int l = blockIdx.z;
    const float* Wl = W + (size_t)l * K * N;
    size_t ob = (size_t)l * lstride;
    int n0 = blockIdx.x * 32, k0 = blockIdx.y * 32;
    int tx = threadIdx.x, ty = threadIdx.y;
#pragma unroll
    for (int r = 0; r < 32; r += 8)
        t[ty + r][tx] = Wl[(size_t)(k0 + ty + r) * N + n0 + tx];
    __syncthreads();
#pragma unroll
    for (int r = 0; r < 32; r += 8) {
        int n = n0 + ty + r;
        int prow;
        if (mode == 0)      prow = rowoff + n;
        else if (mode == 1) prow = ((n >> 6) << 7) + (n & 63);
        else                prow = ((n >> 6) << 7) + 64 + (n & 63);
        o[ob + (size_t)prow * K + k0 + tx] = __float2half(t[tx][ty + r]);
    }
}

// merged QKV weight conversion
__global__ void wconv_qkv_kernel(const float* __restrict__ Wq,
                                 const float* __restrict__ Wk,
                                 const float* __restrict__ Wv,
                                 __half* __restrict__ o) {
    __shared__ float t[32][33];
    int l = blockIdx.z;
    int n0 = blockIdx.x * 32, k0 = blockIdx.y * 32;
    int tx = threadIdx.x, ty = threadIdx.y;
    const float* W; int srcN, coff;
    if (n0 < 1024)      { W = Wq; srcN = 1024; coff = 0; }
    else if (n0 < 1280) { W = Wk; srcN = 256;  coff = 1024; }
    else                { W = Wv; srcN = 256;  coff = 1280; }
    const float* Wl = W + (size_t)l * 1024 * srcN;
    size_t ob = (size_t)l * QKVW * 1024;
#pragma unroll
    for (int r = 0; r < 32; r += 8)
        t[ty + r][tx] = Wl[(size_t)(k0 + ty + r) * srcN + (n0 - coff) + tx];
    __syncthreads();
#pragma unroll
    for (int r = 0; r < 32; r += 8)
        o[ob + (size_t)(n0 + ty + r) * 1024 + k0 + tx] = __float2half(t[tx][ty + r]);
}

__device__ __forceinline__ uint2 pack4h(float v0, float v1, float v2, float v3) {
    __half2 a = __halves2half2(__float2half(v0), __float2half(v1));
    __half2 b = __halves2half2(__float2half(v2), __float2half(v3));
    uint2 r;
    r.x = *(uint32_t*)&a;
    r.y = *(uint32_t*)&b;
    return r;
}

// block-wide sum over 256 threads via shfl + 8-slot smem
__device__ __forceinline__ float bsum256(float v, float* red8, int tid) {
#pragma unroll
    for (int o = 16; o > 0; o >>= 1)
        v += __shfl_xor_sync(0xffffffffu, v, o);
    if ((tid & 31) == 0) red8[tid >> 5] = v;
    __syncthreads();
    float s = red8[0] + red8[1] + red8[2] + red8[3]
            + red8[4] + red8[5] + red8[6] + red8[7];
    return s;
}

__global__ __launch_bounds__(256) void rmsnorm_split_kernel(const float* __restrict__ in,
                                                            const float* __restrict__ scale,
                                                            __half* __restrict__ oh,
                                                            __half* __restrict__ ol) {
    const int t = blockIdx.x;
    const int tid = threadIdx.x;
    __shared__ float red8[8];
    float4 xv = ((const float4*)(in + (size_t)t * DIM))[tid];
    float ss = xv.x * xv.x + xv.y * xv.y + xv.z * xv.z + xv.w * xv.w;
    ss = bsum256(ss, red8, tid);
    const float r = rsqrtf(ss * (1.0f / DIM) + EPS);
    float4 sc = ((const float4*)scale)[tid];
    float v0 = xv.x * r * (1.0f + sc.x);
    float v1 = xv.y * r * (1.0f + sc.y);
    float v2 = xv.z * r * (1.0f + sc.z);
    float v3 = xv.w * r * (1.0f + sc.w);
    uint2 hh = pack4h(v0, v1, v2, v3);
    __half2* hp = (__half2*)&hh;
    float l0 = v0 - __low2float(hp[0]),  l1 = v1 - __high2float(hp[0]);
    float l2 = v2 - __low2float(hp[1]),  l3 = v3 - __high2float(hp[1]);
    ((uint2*)(oh + (size_t)t * DIM))[tid] = hh;
    ((uint2*)(ol + (size_t)t * DIM))[tid] = pack4h(l0, l1, l2, l3);
}

// x += rmsnorm(t, sa); then out = rmsnorm(x, so) -> split fp16
__global__ __launch_bounds__(256) void fuse_norm_kernel(float* __restrict__ x,
                                                        const float* __restrict__ t,
                                                        const float* __restrict__ sa,
                                                        const float* __restrict__ so,
                                                        __half* __restrict__ oh,
                                                        __half* __restrict__ ol) {
    const int tk = blockIdx.x;
    const int tid = threadIdx.x;
    __shared__ float red8[8];
    float4 tv = ((const float4*)(t + (size_t)tk * DIM))[tid];
    float ss = tv.x * tv.x + tv.y * tv.y + tv.z * tv.z + tv.w * tv.w;
    ss = bsum256(ss, red8, tid);
    const float r1 = rsqrtf(ss * (1.0f / DIM) + EPS);
    __syncthreads();   // red8 reuse
    float4 sa4 = ((const float4*)sa)[tid];
    float4* xp4 = (float4*)(x + (size_t)tk * DIM);
    float4 xv = xp4[tid];
    xv.x += tv.x * r1 * (1.0f + sa4.x);
    xv.y += tv.y * r1 * (1.0f + sa4.y);
    xv.z += tv.z * r1 * (1.0f + sa4.z);
    xv.w += tv.w * r1 * (1.0f + sa4.w);
    float ss2 = xv.x * xv.x + xv.y * xv.y + xv.z * xv.z + xv.w * xv.w;
    xp4[tid] = xv;
    ss2 = bsum256(ss2, red8, tid);
    const float r2 = rsqrtf(ss2 * (1.0f / DIM) + EPS);
    float4 so4 = ((const float4*)so)[tid];
    float v0 = xv.x * r2 * (1.0f + so4.x);
    float v1 = xv.y * r2 * (1.0f + so4.y);
    float v2 = xv.z * r2 * (1.0f + so4.z);
    float v3 = xv.w * r2 * (1.0f + so4.w);
    uint2 hh = pack4h(v0, v1, v2, v3);
    __half2* hp = (__half2*)&hh;
    float l0 = v0 - __low2float(hp[0]),  l1 = v1 - __high2float(hp[0]);
    float l2 = v2 - __low2float(hp[1]),  l3 = v3 - __high2float(hp[1]);
    ((uint2*)(oh + (size_t)tk * DIM))[tid] = hh;
    ((uint2*)(ol + (size_t)tk * DIM))[tid] = pack4h(l0, l1, l2, l3);
}

// merged q+k rmsnorm+rope + v convert: blockIdx.y in [0, NH+2*NG)
__global__ __launch_bounds__(64) void qkrope_kernel(float* __restrict__ x,
                                                    const float* __restrict__ qsc,
                                                    const float* __restrict__ ksc,
                                                    const float* __restrict__ cosb,
                                                    const float* __restrict__ sinb,
                                                    __half* __restrict__ kh, __half* __restrict__ kl,
                                                    __half* __restrict__ vh, __half* __restrict__ vl) {
    const int token = blockIdx.x;
    const int hh = blockIdx.y;
    const int pos = token % SEQ;
    const int d = threadIdx.x;

    if (hh >= NH + NG) {   // V: straight 2-limb convert
        const int g = hh - NH - NG;
        float v = x[(size_t)token * QKVW + 1280 + g * HDIM + d];
        __half h = __float2half(v);
        size_t o = ((size_t)token * NG + g) * HDIM + d;
        vh[o] = h;
        vl[o] = __float2half((v - __half2float(h)) * 2048.0f);
        return;
    }

    const float* scale = (hh < NH) ? qsc : ksc;
    const int off = (hh < NH) ? hh * HDIM : 1024 + (hh - NH) * HDIM;
    float* xp = x + (size_t)token * QKVW + off;
    const float val = xp[d];
    __shared__ float sh[HDIM];
    __shared__ float red2[2];
    float ss = val * val;
#pragma unroll
    for (int o = 16; o > 0; o >>= 1)
        ss += __shfl_xor_sync(0xffffffffu, ss, o);
    if ((d & 31) == 0) red2[d >> 5] = ss;
    __syncthreads();
    const float r = rsqrtf((red2[0] + red2[1]) * (1.0f / HDIM) + EPS);
    const float nv = val * r * (1.0f + scale[d]);
    sh[d] = nv;
    __syncthreads();
    const float rot = (d < 32) ? -sh[d + 32] : sh[d - 32];
    const float out = nv * cosb[pos * HDIM + d] + rot * sinb[pos * HDIM + d];
    if (hh < NH) {
        xp[d] = out;
    } else {
        const int g = hh - NH;
        __half h = __float2half(out);
        size_t o = ((size_t)token * NG + g) * HDIM + d;
        kh[o] = h;
        kl[o] = __float2half((out - __half2float(h)) * 2048.0f);
    }
}

// ======================= mma helpers =======================
__device__ __forceinline__ uint32_t smem_u32(const void* p) {
    uint32_t a;
    asm("{ .reg .u64 t; cvta.to.shared.u64 t, %1; cvt.u32.u64 %0, t; }" : "=r"(a) : "l"(p));
    return a;
}
__device__ __forceinline__ void cp16(uint32_t s, const void* g) {
    asm volatile("cp.async.cg.shared.global [%0], [%1], 16;" :: "r"(s), "l"(g));
}
#define LDMX4(r0, r1, r2, r3, addr) \
    asm volatile("ldmatrix.sync.aligned.m8n8.x4.shared.b16 {%0,%1,%2,%3}, [%4];" \
        : "=r"(r0), "=r"(r1), "=r"(r2), "=r"(r3) : "r"(addr))
#define LDMX4T(r0, r1, r2, r3, addr) \
    asm volatile("ldmatrix.sync.aligned.m8n8.x4.trans.shared.b16 {%0,%1,%2,%3}, [%4];" \
        : "=r"(r0), "=r"(r1), "=r"(r2), "=r"(r3) : "r"(addr))
#define MMA16816(d, a, b) \
    asm volatile("mma.sync.aligned.m16n8k16.row.col.f32.f16.f16.f32 " \
        "{%0,%1,%2,%3}, {%4,%5,%6,%7}, {%8,%9}, {%0,%1,%2,%3};" \
        : "+f"((d)[0]), "+f"((d)[1]), "+f"((d)[2]), "+f"((d)[3]) \
        : "r"((a)[0]), "r"((a)[1]), "r"((a)[2]), "r"((a)[3]), "r"((b)[0]), "r"((b)[1]))
#define MMA16816H(d, a, b) \
    asm volatile("mma.sync.aligned.m16n8k16.row.col.f16.f16.f16.f16 " \
        "{%0,%1}, {%2,%3,%4,%5}, {%6,%7}, {%0,%1};" \
        : "+r"((d)[0]), "+r"((d)[1]) \
        : "r"((a)[0]), "r"((a)[1]), "r"((a)[2]), "r"((a)[3]), "r"((b)[0]), "r"((b)[1]))

// ======================= flash attention (tensor core, 2-limb fp16) =======================
#define FSW(r, u) ((r)*128 + (((u) ^ ((r)&7)) << 4))

__device__ __forceinline__ void fa_cvt_store(char* hbuf, char* lbuf, int r, int u,
                                             const float* src, float scale) {
    float4 f0 = *(const float4*)src;
    float4 f1 = *(const float4*)(src + 4);
    float v[8] = {f0.x, f0.y, f0.z, f0.w, f1.x, f1.y, f1.z, f1.w};
    __half hv[8], lv[8];
#pragma unroll
    for (int i = 0; i < 8; i++) {
        float x = v[i] * scale;
        __half hh = __float2half(x);
        hv[i] = hh;
        lv[i] = __float2half((x - __half2float(hh)) * 2048.0f);
    }
    uint32_t off = FSW(r, u);
    *(uint4*)(hbuf + off) = *(uint4*)hv;
    *(uint4*)(lbuf + off) = *(uint4*)lv;
}

__global__ __launch_bounds__(128) void flash_mma(const float* __restrict__ qkv,
                                                 const __half* __restrict__ kh,
                                                 const __half* __restrict__ kl,
                                                 const __half* __restrict__ vh,
                                                 const __half* __restrict__ vl,
                                                 __half* __restrict__ oh,
                                                 __half* __restrict__ ol,
                                                 int window) {
    __shared__ __align__(128) char sm[32768];
    char* khb = sm;
    char* klb = sm + 8192;
    char* vhb = sm + 16384;
    char* vlb = sm + 24576;
    const uint32_t khs = smem_u32(khb);
    const uint32_t kls = khs + 8192;
    const uint32_t vhs = khs + 16384;
    const uint32_t vls = khs + 24576;

    const int qt = blockIdx.x, b = blockIdx.y, h = blockIdx.z;
    const int g = h / GRP;
    const int tid = threadIdx.x;
    const int w = tid >> 5, lane = tid & 31;
    const int q0 = qt * 64;

    // Q tile: fp32 -> hi-limb fragments only (Q-lo dropped; K-lo kept in QK)
    for (int task = tid; task < 512; task += 128) {
        int r = task >> 3, u = task & 7;
        fa_cvt_store(khb, klb, r, u,
                     qkv + (size_t)(b * SEQ + q0 + r) * QKVW + h * HDIM + u * 8, 0.125f);
    }
    __syncthreads();
    uint32_t qfh[4][4];
    {
        int row = w * 16 + (lane & 15);
#pragma unroll
        for (int ks = 0; ks < 4; ks++) {
            int u = ks * 2 + (lane >> 4);
            LDMX4(qfh[ks][0], qfh[ks][1], qfh[ks][2], qfh[ks][3], khs + FSW(row, u));
        }
    }

    float accH[8][4] = {}, accL[8][4] = {};
    float mrun0 = -1e30f, mrun1 = -1e30f, srun0 = 0.f, srun1 = 0.f;

    const int i0 = q0 + w * 16 + (lane >> 2);
    const int i1 = i0 + 8;

    int t0 = 0;
    if (window > 0) { int lo = q0 - window; if (lo > 0) t0 = lo >> 6; }

    for (int kt = t0; kt <= qt; kt++) {
        const int k0 = kt * 64;
        __syncthreads();
        for (int task = tid; task < 512; task += 128) {
            int r = task >> 3, u = task & 7;
            size_t base = ((size_t)(b * SEQ + k0 + r) * NG + g) * HDIM + u * 8;
            uint32_t off = FSW(r, u);
            *(uint4*)(khb + off) = *(const uint4*)(kh + base);
            *(uint4*)(klb + off) = *(const uint4*)(kl + base);
            *(uint4*)(vhb + off) = *(const uint4*)(vh + base);
            *(uint4*)(vlb + off) = *(const uint4*)(vl + base);
        }
        __syncthreads();

        float sH[8][4] = {}, sL[8][4] = {};
#pragma unroll
        for (int ks = 0; ks < 4; ks++) {
            const int bm = lane >> 3;
            const int brow = ((bm >> 1) << 3) + (lane & 7);
            const int bu = ks * 2 + (bm & 1);
#pragma unroll
            for (int p2 = 0; p2 < 4; p2++) {
                uint32_t bh[2][2], bl[2][2];
                uint32_t t0r, t1r, t2r, t3r;
                LDMX4(t0r, t1r, t2r, t3r, khs + FSW(p2 * 16 + brow, bu));
                bh[0][0] = t0r; bh[0][1] = t1r; bh[1][0] = t2r; bh[1][1] = t3r;
                LDMX4(t0r, t1r, t2r, t3r, kls + FSW(p2 * 16 + brow, bu));
                bl[0][0] = t0r; bl[0][1] = t1r; bl[1][0] = t2r; bl[1][1] = t3r;
#pragma unroll
                for (int q2 = 0; q2 < 2; q2++) {
                    int nt = p2 * 2 + q2;
                    MMA16816(sH[nt], qfh[ks], bh[q2]);
                    MMA16816(sL[nt], qfh[ks], bl[q2]);
                }
            }
        }

        float mt0 = -1e30f, mt1 = -1e30f;
#pragma unroll
        for (int nt = 0; nt < 8; nt++) {
            int j0 = k0 + nt * 8 + 2 * (lane & 3);
            int j1 = j0 + 1;
            bool v00 = (j0 <= i0) && (window == 0 || i0 - j0 <= window);
            bool v01 = (j1 <= i0) && (window == 0 || i0 - j1 <= window);
            bool v10 = (j0 <= i1) && (window == 0 || i1 - j0 <= window);
            bool v11 = (j1 <= i1) && (window == 0 || i1 - j1 <= window);
            sH[nt][0] = v00 ? sH[nt][0] + sL[nt][0] * INV2048 : -1e30f;
            sH[nt][1] = v01 ? sH[nt][1] + sL[nt][1] * INV2048 : -1e30f;
            sH[nt][2] = v10 ? sH[nt][2] + sL[nt][2] * INV2048 : -1e30f;
            sH[nt][3] = v11 ? sH[nt][3] + sL[nt][3] * INV2048 : -1e30f;
            mt0 = fmaxf(mt0, fmaxf(sH[nt][0], sH[nt][1]));
            mt1 = fmaxf(mt1, fmaxf(sH[nt][2], sH[nt][3]));
        }
        mt0 = fmaxf(mt0, __shfl_xor_sync(0xffffffffu, mt0, 1));
        mt0 = fmaxf(mt0, __shfl_xor_sync(0xffffffffu, mt0, 2));
        mt1 = fmaxf(mt1, __shfl_xor_sync(0xffffffffu, mt1, 1));
        mt1 = fmaxf(mt1, __shfl_xor_sync(0xffffffffu, mt1, 2));

        const float mn0 = fmaxf(mrun0, mt0);
        const float mn1 = fmaxf(mrun1, mt1);
        const float al0 = __expf(mrun0 - mn0);
        const float al1 = __expf(mrun1 - mn1);
        mrun0 = mn0; mrun1 = mn1;

        float rs0 = 0.f, rs1 = 0.f;
#pragma unroll
        for (int nt = 0; nt < 8; nt++) {
            sH[nt][0] = __expf(sH[nt][0] - mn0);
            sH[nt][1] = __expf(sH[nt][1] - mn0);
            sH[nt][2] = __expf(sH[nt][2] - mn1);
            sH[nt][3] = __expf(sH[nt][3] - mn1);
            rs0 += sH[nt][0] + sH[nt][1];
            rs1 += sH[nt][2] + sH[nt][3];
        }
        rs0 += __shfl_xor_sync(0xffffffffu, rs0, 1);
        rs0 += __shfl_xor_sync(0xffffffffu, rs0, 2);
        rs1 += __shfl_xor_sync(0xffffffffu, rs1, 1);
        rs1 += __shfl_xor_sync(0xffffffffu, rs1, 2);
        srun0 = srun0 * al0 + rs0;
        srun1 = srun1 * al1 + rs1;

#pragma unroll
        for (int nt = 0; nt < 8; nt++) {
            accH[nt][0] *= al0; accH[nt][1] *= al0; accH[nt][2] *= al1; accH[nt][3] *= al1;
            accL[nt][0] *= al0; accL[nt][1] *= al0; accL[nt][2] *= al1; accL[nt][3] *= al1;
        }

        uint32_t pah[4][4], pal[4][4];
#pragma unroll
        for (int j = 0; j < 4; j++) {
#pragma unroll
            for (int q2 = 0; q2 < 2; q2++) {
                int nt = 2 * j + q2;
#pragma unroll
                for (int half_ = 0; half_ < 2; half_++) {
                    float p0 = sH[nt][half_ * 2 + 0];
                    float p1 = sH[nt][half_ * 2 + 1];
                    __half h0 = __float2half(p0), h1 = __float2half(p1);
                    __half l0 = __float2half((p0 - __half2float(h0)) * 2048.0f);
                    __half l1 = __float2half((p1 - __half2float(h1)) * 2048.0f);
                    __half2 hp = __halves2half2(h0, h1);
                    __half2 lp = __halves2half2(l0, l1);
                    pah[j][q2 * 2 + half_] = *(uint32_t*)&hp;
                    pal[j][q2 * 2 + half_] = *(uint32_t*)&lp;
                }
            }
        }

        {
            const int vrow_base = ((lane >> 3) & 1) * 8 + (lane & 7);
            const int vu_add = lane >> 4;
#pragma unroll
            for (int ks = 0; ks < 4; ks++) {
#pragma unroll
                for (int d2 = 0; d2 < 4; d2++) {
                    int row = ks * 16 + vrow_base;
                    int u = 2 * d2 + vu_add;
                    uint32_t t0r, t1r, t2r, t3r;
                    uint32_t vbh[2][2], vbl[2][2];
                    LDMX4T(t0r, t1r, t2r, t3r, vhs + FSW(row, u));
                    vbh[0][0] = t0r; vbh[0][1] = t1r; vbh[1][0] = t2r; vbh[1][1] = t3r;
                    LDMX4T(t0r, t1r, t2r, t3r, vls + FSW(row, u));
                    vbl[0][0] = t0r; vbl[0][1] = t1r; vbl[1][0] = t2r; vbl[1][1] = t3r;
#pragma unroll
                    for (int dd = 0; dd < 2; dd++) {
                        int nt = 2 * d2 + dd;
                        MMA16816(accH[nt], pah[ks], vbh[dd]);
                        MMA16816(accL[nt], pal[ks], vbh[dd]);
                        MMA16816(accL[nt], pah[ks], vbl[dd]);
                    }
                }
            }
        }
    }

    const float inv0 = 1.0f / srun0;
    const float inv1 = 1.0f / srun1;
    const size_t tok0 = (size_t)(b * SEQ) + q0 + w * 16 + (lane >> 2);
    const size_t tok1 = tok0 + 8;
#pragma unroll
    for (int nt = 0; nt < 8; nt++) {
        int col = h * HDIM + nt * 8 + 2 * (lane & 3);
        float o00 = (accH[nt][0] + accL[nt][0] * INV2048) * inv0;
        float o01 = (accH[nt][1] + accL[nt][1] * INV2048) * inv0;
        float o10 = (accH[nt][2] + accL[nt][2] * INV2048) * inv1;
        float o11 = (accH[nt][3] + accL[nt][3] * INV2048) * inv1;
        __half h00 = __float2half(o00), h01 = __float2half(o01);
        __half h10 = __float2half(o10), h11 = __float2half(o11);
        __half2 hi0 = __halves2half2(h00, h01);
        __half2 hi1 = __halves2half2(h10, h11);
        __half2 lo0 = __halves2half2(__float2half(o00 - __half2float(h00)),
                                     __float2half(o01 - __half2float(h01)));
        __half2 lo1 = __halves2half2(__float2half(o10 - __half2float(h10)),
                                     __float2half(o11 - __half2float(h11)));
        *(__half2*)(oh + tok0 * DIM + col) = hi0;
        *(__half2*)(ol + tok0 * DIM + col) = lo0;
        *(__half2*)(oh + tok1 * DIM + col) = hi1;
        *(__half2*)(ol + tok1 * DIM + col) = lo1;
    }
}

// ======================= fp16 GEMM (r13 proven: 4-stage, dual frag, 1 CTA/SM) =======================
#define SSTG      24576
#define NSTAGE    4
#define GSMEM     (NSTAGE*SSTG)   // 96 KB

struct Frag {
    uint32_t a[2][2][4];
    uint32_t b[8][2];
};

template<int TP>
__device__ __forceinline__ void load_frags(Frag& f, uint32_t st, int ks,
                                           int a_r, int a_uadd, int b_r0, int b_uadd) {
#pragma unroll
    for (int mb = 0; mb < 2; mb++) {
        int r = a_r + mb * 16;
        int u = ks * 2 + a_uadd;
        uint32_t off = r * 64 + ((u ^ ((r >> 1) & 3)) << 4);
        LDMX4(f.a[0][mb][0], f.a[0][mb][1], f.a[0][mb][2], f.a[0][mb][3], st + off);
        if (TP)
            LDMX4(f.a[1][mb][0], f.a[1][mb][1], f.a[1][mb][2], f.a[1][mb][3], st + 8192 + off);
    }
#pragma unroll
    for (int qd = 0; qd < 4; qd++) {
        int r = b_r0 + qd * 16;
        int u = ks * 2 + b_uadd;
        uint32_t off = r * 64 + ((u ^ ((r >> 1) & 3)) << 4);
        uint32_t t0, t1, t2, t3;
        LDMX4(t0, t1, t2, t3, st + 16384 + off);
        f.b[2*qd][0] = t0; f.b[2*qd][1] = t1;
        f.b[2*qd+1][0] = t2; f.b[2*qd+1][1] = t3;
    }
}

template<int TP>
__device__ __forceinline__ void do_mma(float accH[2][8][4], uint32_t accL[2][8][2],
                                       const Frag& f) {
#pragma unroll
    for (int mb = 0; mb < 2; mb++)
#pragma unroll
        for (int nb = 0; nb < 8; nb++) {
            MMA16816(accH[mb][nb], f.a[0][mb], f.b[nb]);
            if (TP)
                MMA16816H(accL[mb][nb], f.a[1][mb], f.b[nb]);
        }
}

template<int TP>
__device__ __forceinline__ void stage_load(uint32_t st,
                                           const __half* Ah, const __half* Al,
                                           const __half* Bh,
                                           int m0, int n0, int k0, int K, int tid) {
#pragma unroll
    for (int c = tid; c < 512; c += 256) {
        int r = c >> 2, u = c & 3;
        uint32_t off = r * 64 + ((u ^ ((r >> 1) & 3)) << 4);
        size_t ga = (size_t)(m0 + r) * K + k0 + u * 8;
        size_t gb = (size_t)(n0 + r) * K + k0 + u * 8;
        cp16(st + off,          Ah + ga);
        if (TP)
            cp16(st + 8192 + off, Al + ga);
        cp16(st + 16384 + off,  Bh + gb);
    }
    asm volatile("cp.async.commit_group;" ::: "memory");
}

template<int TP>
__global__ __launch_bounds__(256) void gemm_fp16(
    const __half* __restrict__ Ah, const __half* __restrict__ Al,
    const __half* __restrict__ Bh,
    float* __restrict__ C, __half* __restrict__ oh, __half* __restrict__ ol,
    int N, int K, int silu)
{
    extern __shared__ __align__(128) char smem[];
    const uint32_t sb = smem_u32(smem);
    const int tid = threadIdx.x;
    const int lane = tid & 31;
    const int w = tid >> 5;
    const int wm = w & 3;
    const int wn = w >> 2;
    const int m0 = blockIdx.x * 128;
    const int n0 = blockIdx.y * 128;
    const int niter = K >> 5;

    float accH[2][8][4] = {};
    uint32_t accL[2][8][2] = {};
    Frag f0, f1;

    stage_load<TP>(sb + 0*SSTG, Ah, Al, Bh, m0, n0, 0,  K, tid);
    stage_load<TP>(sb + 1*SSTG, Ah, Al, Bh, m0, n0, 32, K, tid);
    stage_load<TP>(sb + 2*SSTG, Ah, Al, Bh, m0, n0, 64, K, tid);

    const int a_r = wm * 32 + (lane & 15);
    const int a_uadd = lane >> 4;
    const int b_mat = lane >> 3;
    const int b_r0 = wn * 64 + ((b_mat >> 1) << 3) + (lane & 7);
    const int b_uadd = b_mat & 1;

    asm volatile("cp.async.wait_group 1;" ::: "memory");
    __syncthreads();
    load_frags<TP>(f0, sb, 0, a_r, a_uadd, b_r0, b_uadd);

    for (int it = 0; it < niter; it++) {
        const uint32_t st  = sb + (it & 3) * SSTG;
        const uint32_t stn = sb + ((it + 1) & 3) * SSTG;

        load_frags<TP>(f1, st, 1, a_r, a_uadd, b_r0, b_uadd);
        do_mma<TP>(accH, accL, f0);
        if (it + 1 < niter)
            load_frags<TP>(f0, stn, 0, a_r, a_uadd, b_r0, b_uadd);
        do_mma<TP>(accH, accL, f1);

        if ((it + 3) * 32 < K) {
            stage_load<TP>(sb + ((it + 3) & 3) * SSTG, Ah, Al, Bh, m0, n0, (it + 3) * 32, K, tid);
            asm volatile("cp.async.wait_group 1;" ::: "memory");
        } else {
            asm volatile("cp.async.wait_group 0;" ::: "memory");
        }
        __syncthreads();
    }

    if (!silu) {
#pragma unroll
        for (int mb = 0; mb < 2; mb++) {
            int row = m0 + wm * 32 + mb * 16 + (lane >> 2);
#pragma unroll
            for (int nb = 0; nb < 8; nb++) {
                int col = n0 + wn * 64 + nb * 8 + 2 * (lane & 3);
                float c0 = accH[mb][nb][0];
                float c1 = accH[mb][nb][1];
                float c2 = accH[mb][nb][2];
                float c3 = accH[mb][nb][3];
                if (TP) {
                    __half2 l01 = *(__half2*)&accL[mb][nb][0];
                    __half2 l23 = *(__half2*)&accL[mb][nb][1];
                    c0 += __low2float(l01);  c1 += __high2float(l01);
                    c2 += __low2float(l23);  c3 += __high2float(l23);
                }
                *(float2*)(C + (size_t)row * N + col)       = make_float2(c0, c1);
                *(float2*)(C + (size_t)(row + 8) * N + col) = make_float2(c2, c3);
            }
        }
    } else {
        float* smf = (float*)smem;
#pragma unroll
        for (int mb = 0; mb < 2; mb++) {
            int rl = wm * 32 + mb * 16 + (lane >> 2);
#pragma unroll
            for (int nb = 0; nb < 8; nb++) {
                int cl = wn * 64 + nb * 8 + 2 * (lane & 3);
                __half2 l01 = *(__half2*)&accL[mb][nb][0];
                __half2 l23 = *(__half2*)&accL[mb][nb][1];
                smf[rl * 132 + cl]           = accH[mb][nb][0] + __low2float(l01);
                smf[rl * 132 + cl + 1]       = accH[mb][nb][1] + __high2float(l01);
                smf[(rl + 8) * 132 + cl]     = accH[mb][nb][2] + __low2float(l23);
                smf[(rl + 8) * 132 + cl + 1] = accH[mb][nb][3] + __high2float(l23);
            }
        }
        __syncthreads();
        for (int i = tid; i < 128 * 64; i += 256) {
            int r = i >> 6, c = i & 63;
            float v1 = smf[r * 132 + c];
            float v2 = smf[r * 132 + c + 64];
            float s = v1 / (1.0f + __expf(-v1)) * v2;
            size_t o = (size_t)(m0 + r) * FF + (size_t)blockIdx.y * 64 + c;
            __half hv = __float2half(s);
            oh[o] = hv;
            ol[o] = __float2half(s - __half2float(hv));
        }
    }
}

// ======================= host driver =======================
extern "C" void kernel_launch(void* const* d_in, const int* in_sizes, int n_in,
                              void* d_out, int out_size) {
    const int*   ids = (const int*)  d_in[0];
    const float* emb = (const float*)d_in[1];
    const float* Wq  = (const float*)d_in[2];
    const float* Wk  = (const float*)d_in[3];
    const float* Wv  = (const float*)d_in[4];
    const float* Wo  = (const float*)d_in[5];
    const float* W1  = (const float*)d_in[6];
    const float* W2  = (const float*)d_in[7];
    const float* W3  = (const float*)d_in[8];
    const float* n1  = (const float*)d_in[9];
    const float* n2  = (const float*)d_in[10];
    const float* n3  = (const float*)d_in[11];
    const float* n4  = (const float*)d_in[12];
    const float* qn  = (const float*)d_in[13];
    const float* kn  = (const float*)d_in[14];
    const float* nf  = (const float*)d_in[15];
    const float* cosb = (const float*)d_in[16];
    const float* sinb = (const float*)d_in[17];
    float* out = (float*)d_out;

    float *x, *qkv, *t;
    cudaGetSymbolAddress((void**)&x,   g_x);
    cudaGetSymbolAddress((void**)&qkv, g_qkv);
    cudaGetSymbolAddress((void**)&t,   g_t);

    __half *ah, *al, *bh, *bl, *kh, *kl, *vh, *vl, *wqkv, *wo, *w12, *w3, *eh;
    cudaGetSymbolAddress((void**)&ah,   g_a_h);
    cudaGetSymbolAddress((void**)&al,   g_a_l);
    cudaGetSymbolAddress((void**)&bh,   g_b_h);
    cudaGetSymbolAddress((void**)&bl,   g_b_l);
    cudaGetSymbolAddress((void**)&kh,   g_k_h);
    cudaGetSymbolAddress((void**)&kl,   g_k_l);
    cudaGetSymbolAddress((void**)&vh,   g_v_h);
    cudaGetSymbolAddress((void**)&vl,   g_v_l);
    cudaGetSymbolAddress((void**)&wqkv, g_wqkv);
    cudaGetSymbolAddress((void**)&wo,   g_wot);
    cudaGetSymbolAddress((void**)&w12,  g_w12);
    cudaGetSymbolAddress((void**)&w3,   g_w3t);
    cudaGetSymbolAddress((void**)&eh,   g_emb);

    cudaFuncSetAttribute(gemm_fp16<1>, cudaFuncAttributeMaxDynamicSharedMemorySize, GSMEM);
    cudaFuncSetAttribute(gemm_fp16<0>, cudaFuncAttributeMaxDynamicSharedMemorySize, GSMEM);

    const int MT = NTOK / 128;
    dim3 wb(32, 8);

    embed_kernel<<<NTOK, 256>>>(ids, emb, x);
    rmsnorm_split_kernel<<<NTOK, 256>>>(x, n1, ah, al);
    wconv_qkv_kernel<<<dim3(QKVW/32, 1024/32, NL), wb>>>(Wq, Wk, Wv, wqkv);
    gemm_fp16<1><<<dim3(MT, QKVW/128), 256, GSMEM>>>(ah, al, wqkv, qkv, nullptr, nullptr, QKVW, 1024, 0);

    wconv_kernel<<<dim3(1024/32, 1024/32, NL), wb>>>(Wo, wo,  1024, 1024, (size_t)1024*1024, 0, 0);
    wconv_kernel<<<dim3(4096/32, 1024/32, NL), wb>>>(W1, w12, 1024, 4096, (size_t)F2W*1024, 0, 1);
    wconv_kernel<<<dim3(4096/32, 1024/32, NL), wb>>>(W2, w12, 1024, 4096, (size_t)F2W*1024, 0, 2);
    wconv_kernel<<<dim3(1024/32, 4096/32, NL), wb>>>(W3, w3,  4096, 1024, (size_t)4096*1024, 0, 0);
    half_kernel<<<(VOCAB*DIM)/256, 256>>>(emb, eh, VOCAB*DIM);

    for (int l = 0; l < NL; l++) {
        const int window = (l < NL - 4) ? WIN : 0;

        if (l > 0)
            gemm_fp16<1><<<dim3(MT, QKVW/128), 256, GSMEM>>>(ah, al,
                wqkv + (size_t)l*QKVW*1024, qkv, nullptr, nullptr, QKVW, 1024, 0);

        qkrope_kernel<<<dim3(NTOK, NH + 2*NG), 64>>>(qkv, qn + (size_t)l * HDIM,
                                                     kn + (size_t)l * HDIM, cosb, sinb,
                                                     kh, kl, vh, vl);

        flash_mma<<<dim3(SEQ/64, BATCH, NH), 128>>>(qkv, kh, kl, vh, vl, ah, al, window);

        gemm_fp16<1><<<dim3(MT, 1024/128), 256, GSMEM>>>(ah, al,
            wo + (size_t)l*1024*1024, t, nullptr, nullptr, 1024, 1024, 0);

        fuse_norm_kernel<<<NTOK, 256>>>(x, t, n2 + (size_t)l * DIM,
                                        n3 + (size_t)l * DIM, ah, al);

        gemm_fp16<1><<<dim3(MT, F2W/128), 256, GSMEM>>>(ah, al,
            w12 + (size_t)l*F2W*1024, nullptr, bh, bl, F2W, 1024, 1);

        gemm_fp16<1><<<dim3(MT, 1024/128), 256, GSMEM>>>(bh, bl,
            w3 + (size_t)l*1024*4096, t, nullptr, nullptr, 1024, 4096, 0);

        const float* so = (l < NL - 1) ? (n1 + (size_t)(l+1) * DIM) : nf;
        fuse_norm_kernel<<<NTOK, 256>>>(x, t, n4 + (size_t)l * DIM, so, ah, al);
    }

    gemm_fp16<0><<<dim3(MT, VOCAB/128), 256, GSMEM>>>(ah, nullptr, eh, out,
                                                      nullptr, nullptr, VOCAB, 1024, 0);
}

// round 17
// speedup vs baseline: 1.1296x; 1.0459x over previous
#include <cuda_runtime.h>
#include <cuda_fp16.h>
#include <math.h>
#include <stdint.h>

#define BATCH  2
#define SEQ    2048
#define DIM    1024
#define NH     16
#define NG     4
#define GRP    4
#define HDIM   64
#define FF     4096
#define NL     8
#define VOCAB  32000
#define WIN    1024
#define EPS    1e-6f
#define NTOK   (BATCH*SEQ)   // 4096
#define QKVW   1536
#define F2W    8192
#define INV2048 (1.0f/2048.0f)

// ======================= scratch =======================
__device__ float g_x   [NTOK*DIM];
__device__ float g_qkv [NTOK*QKVW];
__device__ float g_t   [NTOK*DIM];

__device__ __align__(128) __half g_a_h[NTOK*DIM];
__device__ __align__(128) __half g_a_l[NTOK*DIM];
__device__ __align__(128) __half g_b_h[NTOK*FF];
__device__ __align__(128) __half g_b_l[NTOK*FF];
__device__ __align__(128) __half g_k_h[NTOK*NG*HDIM];
__device__ __align__(128) __half g_v_h[NTOK*NG*HDIM];
__device__ __align__(128) __half g_v_l[NTOK*NG*HDIM];
__device__ __align__(128) __half g_wqkv[NL*QKVW*1024];
__device__ __align__(128) __half g_wot [NL*1024*1024];
__device__ __align__(128) __half g_w12 [NL*F2W*1024];
__device__ __align__(128) __half g_w3t [NL*1024*4096];
__device__ __align__(128) __half g_emb [VOCAB*DIM];

// ======================= small kernels =======================
__global__ void embed_kernel(const int* __restrict__ ids,
                             const float* __restrict__ emb,
                             float* __restrict__ x) {
    int t = blockIdx.x;
    int id = ids[t];
    const float* e = emb + (size_t)id * DIM;
    float* xp = x + (size_t)t * DIM;
    for (int d = threadIdx.x; d < DIM; d += blockDim.x)
        xp[d] = e[d] * 32.0f;
}

__global__ void half_kernel(const float* __restrict__ in,
                            __half* __restrict__ o, int n) {
    int i = blockIdx.x * 256 + threadIdx.x;
    if (i < n) o[i] = __float2half(in[i]);
}

// transpose to fp16 packed: W [L,K,N] fp32 -> out [L, prow(n), K]
__global__ void wconv_kernel(const float* __restrict__ W,
                             __half* __restrict__ o,
                             int K, int N, size_t lstride, int rowoff, int mode) {
    __shared__ float t[32][33];
    int l = blockIdx.z;
    const float* Wl = W + (size_t)l * K * N;
    size_t ob = (size_t)l * lstride;
    int n0 = blockIdx.x * 32, k0 = blockIdx.y * 32;
    int tx = threadIdx.x, ty = threadIdx.y;
#pragma unroll
    for (int r = 0; r < 32; r += 8)
        t[ty + r][tx] = Wl[(size_t)(k0 + ty + r) * N + n0 + tx];
    __syncthreads();
#pragma unroll
    for (int r = 0; r < 32; r += 8) {
        int n = n0 + ty + r;
        int prow;
        if (mode == 0)      prow = rowoff + n;
        else if (mode == 1) prow = ((n >> 6) << 7) + (n & 63);
        else                prow = ((n >> 6) << 7) + 64 + (n & 63);
        o[ob + (size_t)prow * K + k0 + tx] = __float2half(t[tx][ty + r]);
    }
}

// merged QKV weight conversion
__global__ void wconv_qkv_kernel(const float* __restrict__ Wq,
                                 const float* __restrict__ Wk,
                                 const float* __restrict__ Wv,
                                 __half* __restrict__ o) {
    __shared__ float t[32][33];
    int l = blockIdx.z;
    int n0 = blockIdx.x * 32, k0 = blockIdx.y * 32;
    int tx = threadIdx.x, ty = threadIdx.y;
    const float* W; int srcN, coff;
    if (n0 < 1024)      { W = Wq; srcN = 1024; coff = 0; }
    else if (n0 < 1280) { W = Wk; srcN = 256;  coff = 1024; }
    else                { W = Wv; srcN = 256;  coff = 1280; }
    const float* Wl = W + (size_t)l * 1024 * srcN;
    size_t ob = (size_t)l * QKVW * 1024;
#pragma unroll
    for (int r = 0; r < 32; r += 8)
        t[ty + r][tx] = Wl[(size_t)(k0 + ty + r) * srcN + (n0 - coff) + tx];
    __syncthreads();
#pragma unroll
    for (int r = 0; r < 32; r += 8)
        o[ob + (size_t)(n0 + ty + r) * 1024 + k0 + tx] = __float2half(t[tx][ty + r]);
}

__device__ __forceinline__ uint2 pack4h(float v0, float v1, float v2, float v3) {
    __half2 a = __halves2half2(__float2half(v0), __float2half(v1));
    __half2 b = __halves2half2(__float2half(v2), __float2half(v3));
    uint2 r;
    r.x = *(uint32_t*)&a;
    r.y = *(uint32_t*)&b;
    return r;
}

// block-wide sum over 256 threads via shfl + 8-slot smem
__device__ __forceinline__ float bsum256(float v, float* red8, int tid) {
#pragma unroll
    for (int o = 16; o > 0; o >>= 1)
        v += __shfl_xor_sync(0xffffffffu, v, o);
    if ((tid & 31) == 0) red8[tid >> 5] = v;
    __syncthreads();
    float s = red8[0] + red8[1] + red8[2] + red8[3]
            + red8[4] + red8[5] + red8[6] + red8[7];
    return s;
}

__global__ __launch_bounds__(256) void rmsnorm_split_kernel(const float* __restrict__ in,
                                                            const float* __restrict__ scale,
                                                            __half* __restrict__ oh,
                                                            __half* __restrict__ ol) {
    const int t = blockIdx.x;
    const int tid = threadIdx.x;
    __shared__ float red8[8];
    float4 xv = ((const float4*)(in + (size_t)t * DIM))[tid];
    float ss = xv.x * xv.x + xv.y * xv.y + xv.z * xv.z + xv.w * xv.w;
    ss = bsum256(ss, red8, tid);
    const float r = rsqrtf(ss * (1.0f / DIM) + EPS);
    float4 sc = ((const float4*)scale)[tid];
    float v0 = xv.x * r * (1.0f + sc.x);
    float v1 = xv.y * r * (1.0f + sc.y);
    float v2 = xv.z * r * (1.0f + sc.z);
    float v3 = xv.w * r * (1.0f + sc.w);
    uint2 hh = pack4h(v0, v1, v2, v3);
    __half2* hp = (__half2*)&hh;
    float l0 = v0 - __low2float(hp[0]),  l1 = v1 - __high2float(hp[0]);
    float l2 = v2 - __low2float(hp[1]),  l3 = v3 - __high2float(hp[1]);
    ((uint2*)(oh + (size_t)t * DIM))[tid] = hh;
    ((uint2*)(ol + (size_t)t * DIM))[tid] = pack4h(l0, l1, l2, l3);
}

// x += rmsnorm(t, sa); then out = rmsnorm(x, so) -> split fp16
__global__ __launch_bounds__(256) void fuse_norm_kernel(float* __restrict__ x,
                                                        const float* __restrict__ t,
                                                        const float* __restrict__ sa,
                                                        const float* __restrict__ so,
                                                        __half* __restrict__ oh,
                                                        __half* __restrict__ ol) {
    const int tk = blockIdx.x;
    const int tid = threadIdx.x;
    __shared__ float red8[8];
    float4 tv = ((const float4*)(t + (size_t)tk * DIM))[tid];
    float ss = tv.x * tv.x + tv.y * tv.y + tv.z * tv.z + tv.w * tv.w;
    ss = bsum256(ss, red8, tid);
    const float r1 = rsqrtf(ss * (1.0f / DIM) + EPS);
    __syncthreads();   // red8 reuse
    float4 sa4 = ((const float4*)sa)[tid];
    float4* xp4 = (float4*)(x + (size_t)tk * DIM);
    float4 xv = xp4[tid];
    xv.x += tv.x * r1 * (1.0f + sa4.x);
    xv.y += tv.y * r1 * (1.0f + sa4.y);
    xv.z += tv.z * r1 * (1.0f + sa4.z);
    xv.w += tv.w * r1 * (1.0f + sa4.w);
    float ss2 = xv.x * xv.x + xv.y * xv.y + xv.z * xv.z + xv.w * xv.w;
    xp4[tid] = xv;
    ss2 = bsum256(ss2, red8, tid);
    const float r2 = rsqrtf(ss2 * (1.0f / DIM) + EPS);
    float4 so4 = ((const float4*)so)[tid];
    float v0 = xv.x * r2 * (1.0f + so4.x);
    float v1 = xv.y * r2 * (1.0f + so4.y);
    float v2 = xv.z * r2 * (1.0f + so4.z);
    float v3 = xv.w * r2 * (1.0f + so4.w);
    uint2 hh = pack4h(v0, v1, v2, v3);
    __half2* hp = (__half2*)&hh;
    float l0 = v0 - __low2float(hp[0]),  l1 = v1 - __high2float(hp[0]);
    float l2 = v2 - __low2float(hp[1]),  l3 = v3 - __high2float(hp[1]);
    ((uint2*)(oh + (size_t)tk * DIM))[tid] = hh;
    ((uint2*)(ol + (size_t)tk * DIM))[tid] = pack4h(l0, l1, l2, l3);
}

// merged q+k rmsnorm+rope + v convert: blockIdx.y in [0, NH+2*NG)
// q: norm+rope -> fp32; k: norm+rope -> fp16 hi only; v: 2-limb fp16
__global__ __launch_bounds__(64) void qkrope_kernel(float* __restrict__ x,
                                                    const float* __restrict__ qsc,
                                                    const float* __restrict__ ksc,
                                                    const float* __restrict__ cosb,
                                                    const float* __restrict__ sinb,
                                                    __half* __restrict__ kh,
                                                    __half* __restrict__ vh, __half* __restrict__ vl) {
    const int token = blockIdx.x;
    const int hh = blockIdx.y;
    const int pos = token % SEQ;
    const int d = threadIdx.x;

    if (hh >= NH + NG) {   // V: straight 2-limb convert
        const int g = hh - NH - NG;
        float v = x[(size_t)token * QKVW + 1280 + g * HDIM + d];
        __half h = __float2half(v);
        size_t o = ((size_t)token * NG + g) * HDIM + d;
        vh[o] = h;
        vl[o] = __float2half((v - __half2float(h)) * 2048.0f);
        return;
    }

    const float* scale = (hh < NH) ? qsc : ksc;
    const int off = (hh < NH) ? hh * HDIM : 1024 + (hh - NH) * HDIM;
    float* xp = x + (size_t)token * QKVW + off;
    const float val = xp[d];
    __shared__ float sh[HDIM];
    __shared__ float red2[2];
    float ss = val * val;
#pragma unroll
    for (int o = 16; o > 0; o >>= 1)
        ss += __shfl_xor_sync(0xffffffffu, ss, o);
    if ((d & 31) == 0) red2[d >> 5] = ss;
    __syncthreads();
    const float r = rsqrtf((red2[0] + red2[1]) * (1.0f / HDIM) + EPS);
    const float nv = val * r * (1.0f + scale[d]);
    sh[d] = nv;
    __syncthreads();
    const float rot = (d < 32) ? -sh[d + 32] : sh[d - 32];
    const float out = nv * cosb[pos * HDIM + d] + rot * sinb[pos * HDIM + d];
    if (hh < NH) {
        xp[d] = out;
    } else {
        const int g = hh - NH;
        kh[((size_t)token * NG + g) * HDIM + d] = __float2half(out);
    }
}

// ======================= mma helpers =======================
__device__ __forceinline__ uint32_t smem_u32(const void* p) {
    uint32_t a;
    asm("{ .reg .u64 t; cvta.to.shared.u64 t, %1; cvt.u32.u64 %0, t; }" : "=r"(a) : "l"(p));
    return a;
}
__device__ __forceinline__ void cp16(uint32_t s, const void* g) {
    asm volatile("cp.async.cg.shared.global [%0], [%1], 16;" :: "r"(s), "l"(g));
}
#define LDMX4(r0, r1, r2, r3, addr) \
    asm volatile("ldmatrix.sync.aligned.m8n8.x4.shared.b16 {%0,%1,%2,%3}, [%4];" \
        : "=r"(r0), "=r"(r1), "=r"(r2), "=r"(r3) : "r"(addr))
#define LDMX4T(r0, r1, r2, r3, addr) \
    asm volatile("ldmatrix.sync.aligned.m8n8.x4.trans.shared.b16 {%0,%1,%2,%3}, [%4];" \
        : "=r"(r0), "=r"(r1), "=r"(r2), "=r"(r3) : "r"(addr))
#define MMA16816(d, a, b) \
    asm volatile("mma.sync.aligned.m16n8k16.row.col.f32.f16.f16.f32 " \
        "{%0,%1,%2,%3}, {%4,%5,%6,%7}, {%8,%9}, {%0,%1,%2,%3};" \
        : "+f"((d)[0]), "+f"((d)[1]), "+f"((d)[2]), "+f"((d)[3]) \
        : "r"((a)[0]), "r"((a)[1]), "r"((a)[2]), "r"((a)[3]), "r"((b)[0]), "r"((b)[1]))
#define MMA16816H(d, a, b) \
    asm volatile("mma.sync.aligned.m16n8k16.row.col.f16.f16.f16.f16 " \
        "{%0,%1}, {%2,%3,%4,%5}, {%6,%7}, {%0,%1};" \
        : "+r"((d)[0]), "+r"((d)[1]) \
        : "r"((a)[0]), "r"((a)[1]), "r"((a)[2]), "r"((a)[3]), "r"((b)[0]), "r"((b)[1]))

// ======================= flash attention (QK 1-pass fp16, PV 2-limb) =======================
#define FSW(r, u) ((r)*128 + (((u) ^ ((r)&7)) << 4))

// Q hi-limb only conversion into smem
__device__ __forceinline__ void fa_cvt_store_h(char* hbuf, int r, int u,
                                               const float* src, float scale) {
    float4 f0 = *(const float4*)src;
    float4 f1 = *(const float4*)(src + 4);
    float v[8] = {f0.x, f0.y, f0.z, f0.w, f1.x, f1.y, f1.z, f1.w};
    __half hv[8];
#pragma unroll
    for (int i = 0; i < 8; i++)
        hv[i] = __float2half(v[i] * scale);
    *(uint4*)(hbuf + FSW(r, u)) = *(uint4*)hv;
}

__global__ __launch_bounds__(128) void flash_mma(const float* __restrict__ qkv,
                                                 const __half* __restrict__ kh,
                                                 const __half* __restrict__ vh,
                                                 const __half* __restrict__ vl,
                                                 __half* __restrict__ oh,
                                                 __half* __restrict__ ol,
                                                 int window) {
    __shared__ __align__(128) char sm[24576];
    char* khb = sm;                 // 8KB: K hi (also Q staging)
    char* vhb = sm + 8192;          // 8KB: V hi
    char* vlb = sm + 16384;         // 8KB: V lo
    const uint32_t khs = smem_u32(khb);
    const uint32_t vhs = khs + 8192;
    const uint32_t vls = khs + 16384;

    const int qt = blockIdx.x, b = blockIdx.y, h = blockIdx.z;
    const int g = h / GRP;
    const int tid = threadIdx.x;
    const int w = tid >> 5, lane = tid & 31;
    const int q0 = qt * 64;

    // Q tile: fp32 -> hi-limb fragments (staged through khb)
    for (int task = tid; task < 512; task += 128) {
        int r = task >> 3, u = task & 7;
        fa_cvt_store_h(khb, r, u,
                       qkv + (size_t)(b * SEQ + q0 + r) * QKVW + h * HDIM + u * 8, 0.125f);
    }
    __syncthreads();
    uint32_t qfh[4][4];
    {
        int row = w * 16 + (lane & 15);
#pragma unroll
        for (int ks = 0; ks < 4; ks++) {
            int u = ks * 2 + (lane >> 4);
            LDMX4(qfh[ks][0], qfh[ks][1], qfh[ks][2], qfh[ks][3], khs + FSW(row, u));
        }
    }

    float accH[8][4] = {}, accL[8][4] = {};
    float mrun0 = -1e30f, mrun1 = -1e30f, srun0 = 0.f, srun1 = 0.f;

    const int i0 = q0 + w * 16 + (lane >> 2);
    const int i1 = i0 + 8;

    int t0 = 0;
    if (window > 0) { int lo = q0 - window; if (lo > 0) t0 = lo >> 6; }

    for (int kt = t0; kt <= qt; kt++) {
        const int k0 = kt * 64;
        __syncthreads();
        for (int task = tid; task < 512; task += 128) {
            int r = task >> 3, u = task & 7;
            size_t base = ((size_t)(b * SEQ + k0 + r) * NG + g) * HDIM + u * 8;
            uint32_t off = FSW(r, u);
            *(uint4*)(khb + off) = *(const uint4*)(kh + base);
            *(uint4*)(vhb + off) = *(const uint4*)(vh + base);
            *(uint4*)(vlb + off) = *(const uint4*)(vl + base);
        }
        __syncthreads();

        // QK^T: 1-pass hi x hi
        float sH[8][4] = {};
#pragma unroll
        for (int ks = 0; ks < 4; ks++) {
            const int bm = lane >> 3;
            const int brow = ((bm >> 1) << 3) + (lane & 7);
            const int bu = ks * 2 + (bm & 1);
#pragma unroll
            for (int p2 = 0; p2 < 4; p2++) {
                uint32_t bh[2][2];
                uint32_t t0r, t1r, t2r, t3r;
                LDMX4(t0r, t1r, t2r, t3r, khs + FSW(p2 * 16 + brow, bu));
                bh[0][0] = t0r; bh[0][1] = t1r; bh[1][0] = t2r; bh[1][1] = t3r;
#pragma unroll
                for (int q2 = 0; q2 < 2; q2++)
                    MMA16816(sH[p2 * 2 + q2], qfh[ks], bh[q2]);
            }
        }

        float mt0 = -1e30f, mt1 = -1e30f;
#pragma unroll
        for (int nt = 0; nt < 8; nt++) {
            int j0 = k0 + nt * 8 + 2 * (lane & 3);
            int j1 = j0 + 1;
            bool v00 = (j0 <= i0) && (window == 0 || i0 - j0 <= window);
            bool v01 = (j1 <= i0) && (window == 0 || i0 - j1 <= window);
            bool v10 = (j0 <= i1) && (window == 0 || i1 - j0 <= window);
            bool v11 = (j1 <= i1) && (window == 0 || i1 - j1 <= window);
            sH[nt][0] = v00 ? sH[nt][0] : -1e30f;
            sH[nt][1] = v01 ? sH[nt][1] : -1e30f;
            sH[nt][2] = v10 ? sH[nt][2] : -1e30f;
            sH[nt][3] = v11 ? sH[nt][3] : -1e30f;
            mt0 = fmaxf(mt0, fmaxf(sH[nt][0], sH[nt][1]));
            mt1 = fmaxf(mt1, fmaxf(sH[nt][2], sH[nt][3]));
        }
        mt0 = fmaxf(mt0, __shfl_xor_sync(0xffffffffu, mt0, 1));
        mt0 = fmaxf(mt0, __shfl_xor_sync(0xffffffffu, mt0, 2));
        mt1 = fmaxf(mt1, __shfl_xor_sync(0xffffffffu, mt1, 1));
        mt1 = fmaxf(mt1, __shfl_xor_sync(0xffffffffu, mt1, 2));

        const float mn0 = fmaxf(mrun0, mt0);
        const float mn1 = fmaxf(mrun1, mt1);
        const float al0 = __expf(mrun0 - mn0);
        const float al1 = __expf(mrun1 - mn1);
        mrun0 = mn0; mrun1 = mn1;

        float rs0 = 0.f, rs1 = 0.f;
#pragma unroll
        for (int nt = 0; nt < 8; nt++) {
            sH[nt][0] = __expf(sH[nt][0] - mn0);
            sH[nt][1] = __expf(sH[nt][1] - mn0);
            sH[nt][2] = __expf(sH[nt][2] - mn1);
            sH[nt][3] = __expf(sH[nt][3] - mn1);
            rs0 += sH[nt][0] + sH[nt][1];
            rs1 += sH[nt][2] + sH[nt][3];
        }
        rs0 += __shfl_xor_sync(0xffffffffu, rs0, 1);
        rs0 += __shfl_xor_sync(0xffffffffu, rs0, 2);
        rs1 += __shfl_xor_sync(0xffffffffu, rs1, 1);
        rs1 += __shfl_xor_sync(0xffffffffu, rs1, 2);
        srun0 = srun0 * al0 + rs0;
        srun1 = srun1 * al1 + rs1;

#pragma unroll
        for (int nt = 0; nt < 8; nt++) {
            accH[nt][0] *= al0; accH[nt][1] *= al0; accH[nt][2] *= al1; accH[nt][3] *= al1;
            accL[nt][0] *= al0; accL[nt][1] *= al0; accL[nt][2] *= al1; accL[nt][3] *= al1;
        }

        uint32_t pah[4][4], pal[4][4];
#pragma unroll
        for (int j = 0; j < 4; j++) {
#pragma unroll
            for (int q2 = 0; q2 < 2; q2++) {
                int nt = 2 * j + q2;
#pragma unroll
                for (int half_ = 0; half_ < 2; half_++) {
                    float p0 = sH[nt][half_ * 2 + 0];
                    float p1 = sH[nt][half_ * 2 + 1];
                    __half h0 = __float2half(p0), h1 = __float2half(p1);
                    __half l0 = __float2half((p0 - __half2float(h0)) * 2048.0f);
                    __half l1 = __float2half((p1 - __half2float(h1)) * 2048.0f);
                    __half2 hp = __halves2half2(h0, h1);
                    __half2 lp = __halves2half2(l0, l1);
                    pah[j][q2 * 2 + half_] = *(uint32_t*)&hp;
                    pal[j][q2 * 2 + half_] = *(uint32_t*)&lp;
                }
            }
        }

        {
            const int vrow_base = ((lane >> 3) & 1) * 8 + (lane & 7);
            const int vu_add = lane >> 4;
#pragma unroll
            for (int ks = 0; ks < 4; ks++) {
#pragma unroll
                for (int d2 = 0; d2 < 4; d2++) {
                    int row = ks * 16 + vrow_base;
                    int u = 2 * d2 + vu_add;
                    uint32_t t0r, t1r, t2r, t3r;
                    uint32_t vbh[2][2], vbl[2][2];
                    LDMX4T(t0r, t1r, t2r, t3r, vhs + FSW(row, u));
                    vbh[0][0] = t0r; vbh[0][1] = t1r; vbh[1][0] = t2r; vbh[1][1] = t3r;
                    LDMX4T(t0r, t1r, t2r, t3r, vls + FSW(row, u));
                    vbl[0][0] = t0r; vbl[0][1] = t1r; vbl[1][0] = t2r; vbl[1][1] = t3r;
#pragma unroll
                    for (int dd = 0; dd < 2; dd++) {
                        int nt = 2 * d2 + dd;
                        MMA16816(accH[nt], pah[ks], vbh[dd]);
                        MMA16816(accL[nt], pal[ks], vbh[dd]);
                        MMA16816(accL[nt], pah[ks], vbl[dd]);
                    }
                }
            }
        }
    }

    const float inv0 = 1.0f / srun0;
    const float inv1 = 1.0f / srun1;
    const size_t tok0 = (size_t)(b * SEQ) + q0 + w * 16 + (lane >> 2);
    const size_t tok1 = tok0 + 8;
#pragma unroll
    for (int nt = 0; nt < 8; nt++) {
        int col = h * HDIM + nt * 8 + 2 * (lane & 3);
        float o00 = (accH[nt][0] + accL[nt][0] * INV2048) * inv0;
        float o01 = (accH[nt][1] + accL[nt][1] * INV2048) * inv0;
        float o10 = (accH[nt][2] + accL[nt][2] * INV2048) * inv1;
        float o11 = (accH[nt][3] + accL[nt][3] * INV2048) * inv1;
        __half h00 = __float2half(o00), h01 = __float2half(o01);
        __half h10 = __float2half(o10), h11 = __float2half(o11);
        __half2 hi0 = __halves2half2(h00, h01);
        __half2 hi1 = __halves2half2(h10, h11);
        __half2 lo0 = __halves2half2(__float2half(o00 - __half2float(h00)),
                                     __float2half(o01 - __half2float(h01)));
        __half2 lo1 = __halves2half2(__float2half(o10 - __half2float(h10)),
                                     __float2half(o11 - __half2float(h11)));
        *(__half2*)(oh + tok0 * DIM + col) = hi0;
        *(__half2*)(ol + tok0 * DIM + col) = lo0;
        *(__half2*)(oh + tok1 * DIM + col) = hi1;
        *(__half2*)(ol + tok1 * DIM + col) = lo1;
    }
}

// ======================= fp16 GEMM (r13 proven: 4-stage, dual frag, 1 CTA/SM) =======================
#define SSTG      24576
#define NSTAGE    4
#define GSMEM     (NSTAGE*SSTG)   // 96 KB

struct Frag {
    uint32_t a[2][2][4];
    uint32_t b[8][2];
};

template<int TP>
__device__ __forceinline__ void load_frags(Frag& f, uint32_t st, int ks,
                                           int a_r, int a_uadd, int b_r0, int b_uadd) {
#pragma unroll
    for (int mb = 0; mb < 2; mb++) {
        int r = a_r + mb * 16;
        int u = ks * 2 + a_uadd;
        uint32_t off = r * 64 + ((u ^ ((r >> 1) & 3)) << 4);
        LDMX4(f.a[0][mb][0], f.a[0][mb][1], f.a[0][mb][2], f.a[0][mb][3], st + off);
        if (TP)
            LDMX4(f.a[1][mb][0], f.a[1][mb][1], f.a[1][mb][2], f.a[1][mb][3], st + 8192 + off);
    }
#pragma unroll
    for (int qd = 0; qd < 4; qd++) {
        int r = b_r0 + qd * 16;
        int u = ks * 2 + b_uadd;
        uint32_t off = r * 64 + ((u ^ ((r >> 1) & 3)) << 4);
        uint32_t t0, t1, t2, t3;
        LDMX4(t0, t1, t2, t3, st + 16384 + off);
        f.b[2*qd][0] = t0; f.b[2*qd][1] = t1;
        f.b[2*qd+1][0] = t2; f.b[2*qd+1][1] = t3;
    }
}

template<int TP>
__device__ __forceinline__ void do_mma(float accH[2][8][4], uint32_t accL[2][8][2],
                                       const Frag& f) {
#pragma unroll
    for (int mb = 0; mb < 2; mb++)
#pragma unroll
        for (int nb = 0; nb < 8; nb++) {
            MMA16816(accH[mb][nb], f.a[0][mb], f.b[nb]);
            if (TP)
                MMA16816H(accL[mb][nb], f.a[1][mb], f.b[nb]);
        }
}

template<int TP>
__device__ __forceinline__ void stage_load(uint32_t st,
                                           const __half* Ah, const __half* Al,
                                           const __half* Bh,
                                           int m0, int n0, int k0, int K, int tid) {
#pragma unroll
    for (int c = tid; c < 512; c += 256) {
        int r = c >> 2, u = c & 3;
        uint32_t off = r * 64 + ((u ^ ((r >> 1) & 3)) << 4);
        size_t ga = (size_t)(m0 + r) * K + k0 + u * 8;
        size_t gb = (size_t)(n0 + r) * K + k0 + u * 8;
        cp16(st + off,          Ah + ga);
        if (TP)
            cp16(st + 8192 + off, Al + ga);
        cp16(st + 16384 + off,  Bh + gb);
    }
    asm volatile("cp.async.commit_group;" ::: "memory");
}

template<int TP>
__global__ __launch_bounds__(256) void gemm_fp16(
    const __half* __restrict__ Ah, const __half* __restrict__ Al,
    const __half* __restrict__ Bh,
    float* __restrict__ C, __half* __restrict__ oh, __half* __restrict__ ol,
    int N, int K, int silu)
{
    extern __shared__ __align__(128) char smem[];
    const uint32_t sb = smem_u32(smem);
    const int tid = threadIdx.x;
    const int lane = tid & 31;
    const int w = tid >> 5;
    const int wm = w & 3;
    const int wn = w >> 2;
    const int m0 = blockIdx.x * 128;
    const int n0 = blockIdx.y * 128;
    const int niter = K >> 5;

    float accH[2][8][4] = {};
    uint32_t accL[2][8][2] = {};
    Frag f0, f1;

    stage_load<TP>(sb + 0*SSTG, Ah, Al, Bh, m0, n0, 0,  K, tid);
    stage_load<TP>(sb + 1*SSTG, Ah, Al, Bh, m0, n0, 32, K, tid);
    stage_load<TP>(sb + 2*SSTG, Ah, Al, Bh, m0, n0, 64, K, tid);

    const int a_r = wm * 32 + (lane & 15);
    const int a_uadd = lane >> 4;
    const int b_mat = lane >> 3;
    const int b_r0 = wn * 64 + ((b_mat >> 1) << 3) + (lane & 7);
    const int b_uadd = b_mat & 1;

    asm volatile("cp.async.wait_group 1;" ::: "memory");
    __syncthreads();
    load_frags<TP>(f0, sb, 0, a_r, a_uadd, b_r0, b_uadd);

    for (int it = 0; it < niter; it++) {
        const uint32_t st  = sb + (it & 3) * SSTG;
        const uint32_t stn = sb + ((it + 1) & 3) * SSTG;

        load_frags<TP>(f1, st, 1, a_r, a_uadd, b_r0, b_uadd);
        do_mma<TP>(accH, accL, f0);
        if (it + 1 < niter)
            load_frags<TP>(f0, stn, 0, a_r, a_uadd, b_r0, b_uadd);
        do_mma<TP>(accH, accL, f1);

        if ((it + 3) * 32 < K) {
            stage_load<TP>(sb + ((it + 3) & 3) * SSTG, Ah, Al, Bh, m0, n0, (it + 3) * 32, K, tid);
            asm volatile("cp.async.wait_group 1;" ::: "memory");
        } else {
            asm volatile("cp.async.wait_group 0;" ::: "memory");
        }
        __syncthreads();
    }

    if (!silu) {
#pragma unroll
        for (int mb = 0; mb < 2; mb++) {
            int row = m0 + wm * 32 + mb * 16 + (lane >> 2);
#pragma unroll
            for (int nb = 0; nb < 8; nb++) {
                int col = n0 + wn * 64 + nb * 8 + 2 * (lane & 3);
                float c0 = accH[mb][nb][0];
                float c1 = accH[mb][nb][1];
                float c2 = accH[mb][nb][2];
                float c3 = accH[mb][nb][3];
                if (TP) {
                    __half2 l01 = *(__half2*)&accL[mb][nb][0];
                    __half2 l23 = *(__half2*)&accL[mb][nb][1];
                    c0 += __low2float(l01);  c1 += __high2float(l01);
                    c2 += __low2float(l23);  c3 += __high2float(l23);
                }
                *(float2*)(C + (size_t)row * N + col)       = make_float2(c0, c1);
                *(float2*)(C + (size_t)(row + 8) * N + col) = make_float2(c2, c3);
            }
        }
    } else {
        float* smf = (float*)smem;
#pragma unroll
        for (int mb = 0; mb < 2; mb++) {
            int rl = wm * 32 + mb * 16 + (lane >> 2);
#pragma unroll
            for (int nb = 0; nb < 8; nb++) {
                int cl = wn * 64 + nb * 8 + 2 * (lane & 3);
                __half2 l01 = *(__half2*)&accL[mb][nb][0];
                __half2 l23 = *(__half2*)&accL[mb][nb][1];
                smf[rl * 132 + cl]           = accH[mb][nb][0] + __low2float(l01);
                smf[rl * 132 + cl + 1]       = accH[mb][nb][1] + __high2float(l01);
                smf[(rl + 8) * 132 + cl]     = accH[mb][nb][2] + __low2float(l23);
                smf[(rl + 8) * 132 + cl + 1] = accH[mb][nb][3] + __high2float(l23);
            }
        }
        __syncthreads();
        for (int i = tid; i < 128 * 64; i += 256) {
            int r = i >> 6, c = i & 63;
            float v1 = smf[r * 132 + c];
            float v2 = smf[r * 132 + c + 64];
            float s = v1 / (1.0f + __expf(-v1)) * v2;
            size_t o = (size_t)(m0 + r) * FF + (size_t)blockIdx.y * 64 + c;
            __half hv = __float2half(s);
            oh[o] = hv;
            ol[o] = __float2half(s - __half2float(hv));
        }
    }
}

// ======================= host driver =======================
extern "C" void kernel_launch(void* const* d_in, const int* in_sizes, int n_in,
                              void* d_out, int out_size) {
    const int*   ids = (const int*)  d_in[0];
    const float* emb = (const float*)d_in[1];
    const float* Wq  = (const float*)d_in[2];
    const float* Wk  = (const float*)d_in[3];
    const float* Wv  = (const float*)d_in[4];
    const float* Wo  = (const float*)d_in[5];
    const float* W1  = (const float*)d_in[6];
    const float* W2  = (const float*)d_in[7];
    const float* W3  = (const float*)d_in[8];
    const float* n1  = (const float*)d_in[9];
    const float* n2  = (const float*)d_in[10];
    const float* n3  = (const float*)d_in[11];
    const float* n4  = (const float*)d_in[12];
    const float* qn  = (const float*)d_in[13];
    const float* kn  = (const float*)d_in[14];
    const float* nf  = (const float*)d_in[15];
    const float* cosb = (const float*)d_in[16];
    const float* sinb = (const float*)d_in[17];
    float* out = (float*)d_out;

    float *x, *qkv, *t;
    cudaGetSymbolAddress((void**)&x,   g_x);
    cudaGetSymbolAddress((void**)&qkv, g_qkv);
    cudaGetSymbolAddress((void**)&t,   g_t);

    __half *ah, *al, *bh, *bl, *kh, *vh, *vl, *wqkv, *wo, *w12, *w3, *eh;
    cudaGetSymbolAddress((void**)&ah,   g_a_h);
    cudaGetSymbolAddress((void**)&al,   g_a_l);
    cudaGetSymbolAddress((void**)&bh,   g_b_h);
    cudaGetSymbolAddress((void**)&bl,   g_b_l);
    cudaGetSymbolAddress((void**)&kh,   g_k_h);
    cudaGetSymbolAddress((void**)&vh,   g_v_h);
    cudaGetSymbolAddress((void**)&vl,   g_v_l);
    cudaGetSymbolAddress((void**)&wqkv, g_wqkv);
    cudaGetSymbolAddress((void**)&wo,   g_wot);
    cudaGetSymbolAddress((void**)&w12,  g_w12);
    cudaGetSymbolAddress((void**)&w3,   g_w3t);
    cudaGetSymbolAddress((void**)&eh,   g_emb);

    cudaFuncSetAttribute(gemm_fp16<1>, cudaFuncAttributeMaxDynamicSharedMemorySize, GSMEM);
    cudaFuncSetAttribute(gemm_fp16<0>, cudaFuncAttributeMaxDynamicSharedMemorySize, GSMEM);

    const int MT = NTOK / 128;
    dim3 wb(32, 8);

    embed_kernel<<<NTOK, 256>>>(ids, emb, x);
    rmsnorm_split_kernel<<<NTOK, 256>>>(x, n1, ah, al);
    wconv_qkv_kernel<<<dim3(QKVW/32, 1024/32, NL), wb>>>(Wq, Wk, Wv, wqkv);
    gemm_fp16<1><<<dim3(MT, QKVW/128), 256, GSMEM>>>(ah, al, wqkv, qkv, nullptr, nullptr, QKVW, 1024, 0);

    wconv_kernel<<<dim3(1024/32, 1024/32, NL), wb>>>(Wo, wo,  1024, 1024, (size_t)1024*1024, 0, 0);
    wconv_kernel<<<dim3(4096/32, 1024/32, NL), wb>>>(W1, w12, 1024, 4096, (size_t)F2W*1024, 0, 1);
    wconv_kernel<<<dim3(4096/32, 1024/32, NL), wb>>>(W2, w12, 1024, 4096, (size_t)F2W*1024, 0, 2);
    wconv_kernel<<<dim3(1024/32, 4096/32, NL), wb>>>(W3, w3,  4096, 1024, (size_t)4096*1024, 0, 0);
    half_kernel<<<(VOCAB*DIM)/256, 256>>>(emb, eh, VOCAB*DIM);

    for (int l = 0; l < NL; l++) {
        const int window = (l < NL - 4) ? WIN : 0;

        if (l > 0)
            gemm_fp16<1><<<dim3(MT, QKVW/128), 256, GSMEM>>>(ah, al,
                wqkv + (size_t)l*QKVW*1024, qkv, nullptr, nullptr, QKVW, 1024, 0);

        qkrope_kernel<<<dim3(NTOK, NH + 2*NG), 64>>>(qkv, qn + (size_t)l * HDIM,
                                                     kn + (size_t)l * HDIM, cosb, sinb,
                                                     kh, vh, vl);

        flash_mma<<<dim3(SEQ/64, BATCH, NH), 128>>>(qkv, kh, vh, vl, ah, al, window);

        gemm_fp16<1><<<dim3(MT, 1024/128), 256, GSMEM>>>(ah, al,
            wo + (size_t)l*1024*1024, t, nullptr, nullptr, 1024, 1024, 0);

        fuse_norm_kernel<<<NTOK, 256>>>(x, t, n2 + (size_t)l * DIM,
                                        n3 + (size_t)l * DIM, ah, al);

        gemm_fp16<1><<<dim3(MT, F2W/128), 256, GSMEM>>>(ah, al,
            w12 + (size_t)l*F2W*1024, nullptr, bh, bl, F2W, 1024, 1);

        gemm_fp16<1><<<dim3(MT, 1024/128), 256, GSMEM>>>(bh, bl,
            w3 + (size_t)l*1024*4096, t, nullptr, nullptr, 1024, 4096, 0);

        const float* so = (l < NL - 1) ? (n1 + (size_t)(l+1) * DIM) : nf;
        fuse_norm_kernel<<<NTOK, 256>>>(x, t, n4 + (size_t)l * DIM, so, ah, al);
    }

    gemm_fp16<0><<<dim3(MT, VOCAB/128), 256, GSMEM>>>(ah, nullptr, eh, out,
                                                      nullptr, nullptr, VOCAB, 1024, 0);
}